// round 3
// baseline (speedup 1.0000x reference)
#include <cuda_runtime.h>
#include <math.h>

#define S   2048
#define D   64
#define BH  32

typedef unsigned long long u64;

__device__ float g_NC[BH * S];   // column sums
__device__ float g_RC[BH * S];   // rsqrt(N_C)
__device__ float g_RS[BH * S];   // 1 / rowsum

// ---------- packed fp32x2 helpers ----------
__device__ __forceinline__ u64 pk2(float x, float y) {
    u64 r; asm("mov.b64 %0, {%1, %2};" : "=l"(r) : "f"(x), "f"(y)); return r;
}
__device__ __forceinline__ void upk2(u64 v, float &x, float &y) {
    asm("mov.b64 {%0, %1}, %2;" : "=f"(x), "=f"(y) : "l"(v));
}
__device__ __forceinline__ void ffma2(u64 &d, u64 a, u64 b) {
    asm("fma.rn.f32x2 %0, %1, %2, %0;" : "+l"(d) : "l"(a), "l"(b));
}
__device__ __forceinline__ u64 fma2n(u64 a, u64 b, u64 c) {
    u64 d; asm("fma.rn.f32x2 %0, %1, %2, %3;" : "=l"(d) : "l"(a), "l"(b), "l"(c)); return d;
}
__device__ __forceinline__ u64 mul2(u64 a, u64 b) {
    u64 d; asm("mul.rn.f32x2 %0, %1, %2;" : "=l"(d) : "l"(a), "l"(b)); return d;
}
__device__ __forceinline__ u64 add2(u64 a, u64 b) {
    u64 d; asm("add.rn.f32x2 %0, %1, %2;" : "=l"(d) : "l"(a), "l"(b)); return d;
}

// ============================================================================
// Kernel 1: raw scores + column sums.
// Tile 128q x 128k, 256 thr, per-thread 8q(pairs) x 8n. A packed, B broadcast.
// smem: Qt[64][132] k-major Q (packed-pair loads), Ks[64][130] k-major K.
// ============================================================================
#define QT 132
#define KT 130
#define K1_SMEM ((64 * QT + 64 * KT) * 4)

__global__ __launch_bounds__(256, 2)
void k_scores(const float* __restrict__ Qg_, const float* __restrict__ Kg_,
              float* __restrict__ attn) {
    extern __shared__ float sm[];
    float* Qt = sm;             // [64][132]
    float* Ks = sm + 64 * QT;   // [64][130]

    const int kb = blockIdx.x * 128, bh = blockIdx.y, tid = threadIdx.x;
    const int tq = tid >> 4, tn = tid & 15;
    const int lane4 = tid & 3, mrow = (tid >> 2) & 31, grp = tid >> 7;

    const float* Qg = Qg_ + (size_t)bh * S * D;
    const float* Kg = Kg_ + (size_t)bh * S * D;
    float*       Ag = attn + (size_t)bh * S * S;

    // stage K once (k-major, conflict-free STS: warp = 8 n x 4 c4)
#pragma unroll
    for (int it = 0; it < 8; it++) {
        int n  = mrow + 32 * (grp + 2 * (it >> 2));
        int c4 = lane4 + 4 * (it & 3);
        float4 v = *(const float4*)(Kg + (size_t)(kb + n) * D + c4 * 4);
        Ks[(c4 * 4 + 0) * KT + n] = v.x;
        Ks[(c4 * 4 + 1) * KT + n] = v.y;
        Ks[(c4 * 4 + 2) * KT + n] = v.z;
        Ks[(c4 * 4 + 3) * KT + n] = v.w;
    }

    float cs[8];
#pragma unroll
    for (int u = 0; u < 8; u++) cs[u] = 0.f;

    for (int qb = 0; qb < S; qb += 128) {
        __syncthreads();
#pragma unroll
        for (int it = 0; it < 8; it++) {
            int m  = mrow + 32 * (grp + 2 * (it >> 2));
            int c4 = lane4 + 4 * (it & 3);
            float4 v = *(const float4*)(Qg + (size_t)(qb + m) * D + c4 * 4);
            Qt[(c4 * 4 + 0) * QT + m] = v.x;
            Qt[(c4 * 4 + 1) * QT + m] = v.y;
            Qt[(c4 * 4 + 2) * QT + m] = v.z;
            Qt[(c4 * 4 + 3) * QT + m] = v.w;
        }
        __syncthreads();

        u64 acc[4][8];
#pragma unroll
        for (int p = 0; p < 4; p++)
#pragma unroll
            for (int u = 0; u < 8; u++) acc[p][u] = 0ull;

#pragma unroll 8
        for (int kk = 0; kk < 64; kk++) {
            const float* qrow = Qt + kk * QT + tq * 8;
            ulonglong2 a01 = *(const ulonglong2*)qrow;
            ulonglong2 a23 = *(const ulonglong2*)(qrow + 4);
            u64 ap[4] = {a01.x, a01.y, a23.x, a23.y};
            const float* krow = Ks + kk * KT + tn;
            u64 bd[8];
#pragma unroll
            for (int u = 0; u < 8; u++) { float b = krow[16 * u]; bd[u] = pk2(b, b); }
#pragma unroll
            for (int p = 0; p < 4; p++)
#pragma unroll
                for (int u = 0; u < 8; u++) ffma2(acc[p][u], ap[p], bd[u]);
        }

        // epilogue: packed transform s = exp(-acos(1-t)^2), t = 1-dot.
        // acos(1-t)^2 = 2t * P(t)^2, P = deg-9 Taylor of acos(1-t)/sqrt(2t).
        const u64 ONE  = pk2(1.f, 1.f);
        const u64 NONE = pk2(-1.f, -1.f);
        const u64 C9 = pk2(1.9066e-5f, 1.9066e-5f);
        const u64 C8 = pk2(4.5125e-5f, 4.5125e-5f);
        const u64 C7 = pk2(1.09101e-4f, 1.09101e-4f);
        const u64 C6 = pk2(2.71137e-4f, 2.71137e-4f);
        const u64 C5 = pk2(6.99129e-4f, 6.99129e-4f);
        const u64 C4 = pk2(1.89887e-3f, 1.89887e-3f);
        const u64 C3 = pk2(5.58036e-3f, 5.58036e-3f);
        const u64 C2 = pk2(1.875e-2f, 1.875e-2f);
        const u64 C1 = pk2(8.3333333e-2f, 8.3333333e-2f);
#pragma unroll
        for (int p = 0; p < 4; p++) {
            int r0 = qb + tq * 8 + 2 * p;
#pragma unroll
            for (int u = 0; u < 8; u++) {
                u64 t  = fma2n(acc[p][u], NONE, ONE);
                u64 pv = fma2n(C9, t, C8);
                pv = fma2n(pv, t, C7);
                pv = fma2n(pv, t, C6);
                pv = fma2n(pv, t, C5);
                pv = fma2n(pv, t, C4);
                pv = fma2n(pv, t, C3);
                pv = fma2n(pv, t, C2);
                pv = fma2n(pv, t, C1);
                pv = fma2n(pv, t, ONE);
                u64 phi = mul2(add2(t, t), mul2(pv, pv));
                float f0, f1; upk2(phi, f0, f1);
                float s0 = __expf(-f0), s1 = __expf(-f1);
                cs[u] += s0 + s1;
                size_t col = (size_t)kb + tn + 16 * u;
                __stcs(Ag + (size_t)r0 * S + col, s0);
                __stcs(Ag + (size_t)(r0 + 1) * S + col, s1);
            }
        }
    }

    // deterministic column-sum reduction (reuse smem)
    __syncthreads();
    float* red = sm;
#pragma unroll
    for (int u = 0; u < 8; u++) red[tq * 128 + tn + 16 * u] = cs[u];
    __syncthreads();
    if (tid < 128) {
        float t = 0.f;
#pragma unroll
        for (int i = 0; i < 16; i++) t += red[i * 128 + tid];
        g_NC[bh * S + kb + tid] = t;
    }
}

// ============================================================================
// Kernel 2: rc = rsqrt(N_C)
// ============================================================================
__global__ void k_prep() {
    int i = blockIdx.x * 256 + threadIdx.x;
    if (i < BH * S) g_RC[i] = rsqrtf(g_NC[i]);
}

// ============================================================================
// Kernel 3: rowsums. rinv[q] = 1 / sum_k s[q,k]*rc[k].
// ============================================================================
__global__ __launch_bounds__(256)
void k_rowsum(const float* __restrict__ attn) {
    const int bh = blockIdx.y;
    const int q0 = blockIdx.x * 64;
    const int w  = threadIdx.x >> 5;
    const int l  = threadIdx.x & 31;

    const float4* rc4 = (const float4*)(g_RC + bh * S);
    const float*  Ag  = attn + (size_t)bh * S * S;

    float acc[8];
#pragma unroll
    for (int r = 0; r < 8; r++) acc[r] = 0.f;
    const float4* row[8];
#pragma unroll
    for (int r = 0; r < 8; r++)
        row[r] = (const float4*)(Ag + (size_t)(q0 + w * 8 + r) * S);

#pragma unroll 2
    for (int step = 0; step < 16; step++) {
        int c = step * 32 + l;
        float4 rcv = __ldg(&rc4[c]);
#pragma unroll
        for (int r = 0; r < 8; r++) {
            float4 sv = __ldcs(&row[r][c]);
            acc[r] += sv.x * rcv.x + sv.y * rcv.y + sv.z * rcv.z + sv.w * rcv.w;
        }
    }
#pragma unroll
    for (int r = 0; r < 8; r++) {
#pragma unroll
        for (int off = 16; off; off >>= 1)
            acc[r] += __shfl_xor_sync(0xffffffffu, acc[r], off);
    }
    if (l == 0) {
#pragma unroll
        for (int r = 0; r < 8; r++)
            g_RS[bh * S + q0 + w * 8 + r] = 1.0f / acc[r];
    }
}

// ============================================================================
// Kernel 4: weights + AV GEMM. 128-thr blocks, tile 128q x 64d, k-chunk 64.
// Per-thread 8q(pairs) x 8d (d split {td*4, 32+td*4}). W packed, V broadcast.
// smem: Ws[64][132] k-major weights, Vs[64][72] natural V.
// ============================================================================
#define WT 132
#define VT 72
#define KW_SMEM ((64 * WT + 64 * VT) * 4)

__global__ __launch_bounds__(128, 4)
void k_wav(const float* __restrict__ Vg_, float* __restrict__ attn,
           float* __restrict__ Og_) {
    extern __shared__ float sm[];
    float* Ws = sm;
    float* Vs = sm + 64 * WT;

    const int bh = blockIdx.y, qb = blockIdx.x * 128, tid = threadIdx.x;
    const int tq = tid >> 3, td = tid & 7;
    const int lane4 = tid & 3, mrow = (tid >> 2) & 31;

    float*       Ag = attn + (size_t)bh * S * S;
    const float* Vg = Vg_ + (size_t)bh * S * D;
    float*       Og = Og_ + (size_t)bh * S * D;
    const float* rcg = g_RC + bh * S;
    const float* rig = g_RS + bh * S;

    u64 acc[4][8];
#pragma unroll
    for (int p = 0; p < 4; p++)
#pragma unroll
        for (int u = 0; u < 8; u++) acc[p][u] = 0ull;

    for (int cb = 0; cb < S; cb += 64) {
        __syncthreads();
        // stage W: rescale, write final weights back, store k-major
#pragma unroll
        for (int it = 0; it < 16; it++) {
            int m  = mrow + 32 * (it & 3);
            int c4 = lane4 + 4 * (it >> 2);
            float* gp = Ag + (size_t)(qb + m) * S + cb + c4 * 4;
            float4 sv = __ldcs((const float4*)gp);
            float  ri = __ldg(rig + qb + m);
            float4 rc = __ldg((const float4*)(rcg + cb + c4 * 4));
            float4 wv;
            wv.x = sv.x * rc.x * ri;
            wv.y = sv.y * rc.y * ri;
            wv.z = sv.z * rc.z * ri;
            wv.w = sv.w * rc.w * ri;
            __stcs((float4*)gp, wv);
            Ws[(c4 * 4 + 0) * WT + m] = wv.x;
            Ws[(c4 * 4 + 1) * WT + m] = wv.y;
            Ws[(c4 * 4 + 2) * WT + m] = wv.z;
            Ws[(c4 * 4 + 3) * WT + m] = wv.w;
        }
        // stage V natural
#pragma unroll
        for (int it = 0; it < 8; it++) {
            int idx = tid + 128 * it;
            int k = idx >> 4, c4 = idx & 15;
            *(float4*)(Vs + k * VT + c4 * 4) =
                *(const float4*)(Vg + (size_t)(cb + k) * D + c4 * 4);
        }
        __syncthreads();

#pragma unroll 8
        for (int kk = 0; kk < 64; kk++) {
            const float* wrow = Ws + kk * WT + tq * 8;
            ulonglong2 a01 = *(const ulonglong2*)wrow;
            ulonglong2 a23 = *(const ulonglong2*)(wrow + 4);
            u64 ap[4] = {a01.x, a01.y, a23.x, a23.y};
            float4 b0 = *(const float4*)(Vs + kk * VT + td * 4);
            float4 b1 = *(const float4*)(Vs + kk * VT + 32 + td * 4);
            u64 bd[8] = {pk2(b0.x, b0.x), pk2(b0.y, b0.y), pk2(b0.z, b0.z), pk2(b0.w, b0.w),
                         pk2(b1.x, b1.x), pk2(b1.y, b1.y), pk2(b1.z, b1.z), pk2(b1.w, b1.w)};
#pragma unroll
            for (int p = 0; p < 4; p++)
#pragma unroll
                for (int u = 0; u < 8; u++) ffma2(acc[p][u], ap[p], bd[u]);
        }
    }

    // store O
#pragma unroll
    for (int p = 0; p < 4; p++) {
        float lo[8], hi[8];
#pragma unroll
        for (int u = 0; u < 8; u++) upk2(acc[p][u], lo[u], hi[u]);
        int r0 = qb + tq * 8 + 2 * p;
        *(float4*)(Og + (size_t)r0 * D + td * 4)            = make_float4(lo[0], lo[1], lo[2], lo[3]);
        *(float4*)(Og + (size_t)r0 * D + 32 + td * 4)       = make_float4(lo[4], lo[5], lo[6], lo[7]);
        *(float4*)(Og + (size_t)(r0 + 1) * D + td * 4)      = make_float4(hi[0], hi[1], hi[2], hi[3]);
        *(float4*)(Og + (size_t)(r0 + 1) * D + 32 + td * 4) = make_float4(hi[4], hi[5], hi[6], hi[7]);
    }
}

// ============================================================================
extern "C" void kernel_launch(void* const* d_in, const int* in_sizes, int n_in,
                              void* d_out, int out_size) {
    const float* q = (const float*)d_in[0];
    const float* k = (const float*)d_in[1];
    const float* v = (const float*)d_in[2];
    // d_in[3] = attn_mask (all False) — no-op in reference.

    float* out  = (float*)d_out;
    float* O    = out;                       // [B,H,S,D]
    float* attn = out + (size_t)BH * S * D;  // [B,H,S,S]

    cudaFuncSetAttribute(k_scores, cudaFuncAttributeMaxDynamicSharedMemorySize, K1_SMEM);
    cudaFuncSetAttribute(k_wav,    cudaFuncAttributeMaxDynamicSharedMemorySize, KW_SMEM);

    dim3 g1(S / 128, BH);
    k_scores<<<g1, 256, K1_SMEM>>>(q, k, attn);

    k_prep<<<(BH * S + 255) / 256, 256>>>();

    dim3 g3(S / 64, BH);
    k_rowsum<<<g3, 256>>>(attn);

    dim3 g4(S / 128, BH);
    k_wav<<<g4, 128, KW_SMEM>>>(v, attn, O);
}

// round 8
// speedup vs baseline: 2.0260x; 2.0260x over previous
#include <cuda_runtime.h>
#include <cuda_bf16.h>
#include <math.h>

#define S   2048
#define D   64
#define BH  32

typedef unsigned long long u64;
typedef unsigned int u32;

// scratch
__device__ float g_NC[BH * S];
__device__ float g_RC[BH * S];
__device__ float g_RS[BH * S];
__device__ __nv_bfloat16 g_Qhi[BH * S * D];
__device__ __nv_bfloat16 g_Qlo[BH * S * D];
__device__ __nv_bfloat16 g_Khi[BH * S * D];
__device__ __nv_bfloat16 g_Klo[BH * S * D];
__device__ __nv_bfloat16 g_Vhi[BH * S * D];
__device__ __nv_bfloat16 g_Vlo[BH * S * D];

// ---------- packed fp32x2 helpers ----------
__device__ __forceinline__ u64 pk2(float x, float y) {
    u64 r; asm("mov.b64 %0, {%1, %2};" : "=l"(r) : "f"(x), "f"(y)); return r;
}
__device__ __forceinline__ void upk2(u64 v, float &x, float &y) {
    asm("mov.b64 {%0, %1}, %2;" : "=f"(x), "=f"(y) : "l"(v));
}
__device__ __forceinline__ u64 fma2n(u64 a, u64 b, u64 c) {
    u64 d; asm("fma.rn.f32x2 %0, %1, %2, %3;" : "=l"(d) : "l"(a), "l"(b), "l"(c)); return d;
}
__device__ __forceinline__ u64 mul2(u64 a, u64 b) {
    u64 d; asm("mul.rn.f32x2 %0, %1, %2;" : "=l"(d) : "l"(a), "l"(b)); return d;
}
__device__ __forceinline__ u64 add2(u64 a, u64 b) {
    u64 d; asm("add.rn.f32x2 %0, %1, %2;" : "=l"(d) : "l"(a), "l"(b)); return d;
}

// s = exp(-acos(1-t)^2): acos(1-t)^2 = 2t*P(t)^2, P = deg-9 Taylor of acos(1-t)/sqrt(2t)
__device__ __forceinline__ void xf2(float x0, float x1, float &s0, float &s1) {
    const u64 ONE  = pk2(1.f, 1.f);
    const u64 NONE = pk2(-1.f, -1.f);
    u64 t = fma2n(pk2(x0, x1), NONE, ONE);
    u64 p = fma2n(pk2(1.9066e-5f, 1.9066e-5f), t, pk2(4.5125e-5f, 4.5125e-5f));
    p = fma2n(p, t, pk2(1.09101e-4f, 1.09101e-4f));
    p = fma2n(p, t, pk2(2.71137e-4f, 2.71137e-4f));
    p = fma2n(p, t, pk2(6.99129e-4f, 6.99129e-4f));
    p = fma2n(p, t, pk2(1.89887e-3f, 1.89887e-3f));
    p = fma2n(p, t, pk2(5.58036e-3f, 5.58036e-3f));
    p = fma2n(p, t, pk2(1.875e-2f, 1.875e-2f));
    p = fma2n(p, t, pk2(8.3333333e-2f, 8.3333333e-2f));
    p = fma2n(p, t, ONE);
    u64 phi = mul2(add2(t, t), mul2(p, p));
    float f0, f1; upk2(phi, f0, f1);
    s0 = __expf(-f0);
    s1 = __expf(-f1);
}

// ---------- mma / ldmatrix helpers (legacy path, valid on plain sm_103) ----------
__device__ __forceinline__ u32 smem_u32(const void* p) {
    u32 a;
    asm("{ .reg .u64 t; cvta.to.shared.u64 t, %1; cvt.u32.u64 %0, t; }" : "=r"(a) : "l"(p));
    return a;
}
__device__ __forceinline__ void ldm4(u32 addr, u32 r[4]) {
    asm volatile("ldmatrix.sync.aligned.m8n8.x4.shared.b16 {%0,%1,%2,%3}, [%4];"
                 : "=r"(r[0]), "=r"(r[1]), "=r"(r[2]), "=r"(r[3]) : "r"(addr));
}
__device__ __forceinline__ void ldm4t(u32 addr, u32 r[4]) {
    asm volatile("ldmatrix.sync.aligned.m8n8.x4.trans.shared.b16 {%0,%1,%2,%3}, [%4];"
                 : "=r"(r[0]), "=r"(r[1]), "=r"(r[2]), "=r"(r[3]) : "r"(addr));
}
__device__ __forceinline__ void mma_bf16(float c[4], const u32 a[4], u32 b0, u32 b1) {
    asm volatile(
        "mma.sync.aligned.m16n8k16.row.col.f32.bf16.bf16.f32 "
        "{%0,%1,%2,%3}, {%4,%5,%6,%7}, {%8,%9}, {%0,%1,%2,%3};"
        : "+f"(c[0]), "+f"(c[1]), "+f"(c[2]), "+f"(c[3])
        : "r"(a[0]), "r"(a[1]), "r"(a[2]), "r"(a[3]), "r"(b0), "r"(b1));
}

#define PADW 72   // bf16 elems per row (64 + 8 pad); 144B stride -> ldmatrix conflict-free

// ============================================================================
// Kernel 0: fp32 -> bf16 hi/lo split for Q, K, V
// ============================================================================
__global__ void k_convert(const float* __restrict__ q, const float* __restrict__ k,
                          const float* __restrict__ v) {
    int i = blockIdx.x * 256 + threadIdx.x;
    const int n4 = BH * S * D / 4;
    if (i >= n4) return;
    const float4* src;
    __nv_bfloat16 *hi, *lo;
    if (blockIdx.y == 0)      { src = (const float4*)q; hi = g_Qhi; lo = g_Qlo; }
    else if (blockIdx.y == 1) { src = (const float4*)k; hi = g_Khi; lo = g_Klo; }
    else                      { src = (const float4*)v; hi = g_Vhi; lo = g_Vlo; }
    float4 w = src[i];
    __nv_bfloat16 hx = __float2bfloat16(w.x), hy = __float2bfloat16(w.y);
    __nv_bfloat16 hz = __float2bfloat16(w.z), hw = __float2bfloat16(w.w);
    ushort4 h, l;
    h.x = __bfloat16_as_ushort(hx); h.y = __bfloat16_as_ushort(hy);
    h.z = __bfloat16_as_ushort(hz); h.w = __bfloat16_as_ushort(hw);
    l.x = __bfloat16_as_ushort(__float2bfloat16(w.x - __bfloat162float(hx)));
    l.y = __bfloat16_as_ushort(__float2bfloat16(w.y - __bfloat162float(hy)));
    l.z = __bfloat16_as_ushort(__float2bfloat16(w.z - __bfloat162float(hz)));
    l.w = __bfloat16_as_ushort(__float2bfloat16(w.w - __bfloat162float(hw)));
    *(ushort4*)(hi + 4 * (size_t)i) = h;
    *(ushort4*)(lo + 4 * (size_t)i) = l;
}

// ============================================================================
// Kernel 1: scores via HMMA bf16x3. Block 256thr = 8 warps (2q x 4k).
// Tile 128q x 128k; K resident; loop 16 q-tiles. Warp: 64q x 32k.
// smem: Bhi|Blo|Ahi|Alo [128][72] bf16 + colsum scratch 256 floats.
// ============================================================================
#define SC_SMEM (4 * 128 * PADW * 2 + 1024)

__global__ __launch_bounds__(256, 2)
void k_scores_mma(float* __restrict__ attn) {
    extern __shared__ char smc[];
    __nv_bfloat16* Bhi = (__nv_bfloat16*)smc;
    __nv_bfloat16* Blo = Bhi + 128 * PADW;
    __nv_bfloat16* Ahi = Blo + 128 * PADW;
    __nv_bfloat16* Alo = Ahi + 128 * PADW;
    float* scr = (float*)(smc + 4 * 128 * PADW * 2);

    const int kbG = blockIdx.x * 128, bh = blockIdx.y;
    const int tid = threadIdx.x, wid = tid >> 5, lane = tid & 31;
    const int wq = wid >> 2, wk = wid & 3;
    const int grp = lane >> 2, tig = lane & 3;
    const int r8 = lane & 7, ts = lane >> 3;

    const __nv_bfloat16* QhiG = g_Qhi + (size_t)bh * S * D;
    const __nv_bfloat16* QloG = g_Qlo + (size_t)bh * S * D;
    const __nv_bfloat16* KhiG = g_Khi + (size_t)bh * S * D;
    const __nv_bfloat16* KloG = g_Klo + (size_t)bh * S * D;
    float* Ag = attn + (size_t)bh * S * S;

    // stage K (resident)
#pragma unroll
    for (int i = 0; i < 4; i++) {
        int idx = tid + 256 * i, row = idx >> 3, c8 = idx & 7;
        *(uint4*)(Bhi + row * PADW + c8 * 8) = *(const uint4*)(KhiG + (size_t)(kbG + row) * D + c8 * 8);
        *(uint4*)(Blo + row * PADW + c8 * 8) = *(const uint4*)(KloG + (size_t)(kbG + row) * D + c8 * 8);
    }

    const u32 sBh = smem_u32(Bhi), sBl = smem_u32(Blo);
    const u32 sAh = smem_u32(Ahi), sAl = smem_u32(Alo);
    // A frag: row = wq*64 + t*16 + (ts&1)*8 + r8, col = ks*16 + (ts>>1)*8
    const u32 aOff = (u32)(((wq * 64 + (ts & 1) * 8 + r8) * PADW + (ts >> 1) * 8) * 2);
    // B frag (non-trans): n = wk*32 + p*16 + ((ts>>1)&1)*8 + r8, col = ks*16 + (ts&1)*8
    const u32 bOff = (u32)(((wk * 32 + ((ts >> 1) & 1) * 8 + r8) * PADW + (ts & 1) * 8) * 2);

    float colacc[4][2];
#pragma unroll
    for (int n = 0; n < 4; n++) { colacc[n][0] = 0.f; colacc[n][1] = 0.f; }

    for (int it = 0; it < 16; it++) {
        const int qb = it * 128;
        __syncthreads();
#pragma unroll
        for (int i = 0; i < 4; i++) {
            int idx = tid + 256 * i, row = idx >> 3, c8 = idx & 7;
            *(uint4*)(Ahi + row * PADW + c8 * 8) = *(const uint4*)(QhiG + (size_t)(qb + row) * D + c8 * 8);
            *(uint4*)(Alo + row * PADW + c8 * 8) = *(const uint4*)(QloG + (size_t)(qb + row) * D + c8 * 8);
        }
        __syncthreads();

        float acc[4][4][4];
#pragma unroll
        for (int t = 0; t < 4; t++)
#pragma unroll
            for (int n = 0; n < 4; n++)
#pragma unroll
                for (int c = 0; c < 4; c++) acc[t][n][c] = 0.f;

#pragma unroll
        for (int ks = 0; ks < 4; ks++) {
            u32 bfh0[4], bfh1[4], bfl0[4], bfl1[4];
            ldm4(sBh + bOff + ks * 32, bfh0);
            ldm4(sBh + bOff + 2304 + ks * 32, bfh1);
            ldm4(sBl + bOff + ks * 32, bfl0);
            ldm4(sBl + bOff + 2304 + ks * 32, bfl1);
#pragma unroll
            for (int t = 0; t < 4; t++) {
                u32 ah[4], al[4];
                ldm4(sAh + aOff + t * 2304 + ks * 32, ah);
                ldm4(sAl + aOff + t * 2304 + ks * 32, al);
#pragma unroll
                for (int n = 0; n < 4; n++) {
                    const u32* bp = (n < 2) ? bfh0 : bfh1;
                    const u32* lp = (n < 2) ? bfl0 : bfl1;
                    int h = (n & 1) * 2;
                    mma_bf16(acc[t][n], ah, bp[h], bp[h + 1]);
                    mma_bf16(acc[t][n], ah, lp[h], lp[h + 1]);
                    mma_bf16(acc[t][n], al, bp[h], bp[h + 1]);
                }
            }
        }

        // epilogue: transform + store + colsum accumulate
#pragma unroll
        for (int t = 0; t < 4; t++) {
            int row0 = qb + wq * 64 + t * 16 + grp;
#pragma unroll
            for (int n = 0; n < 4; n++) {
                float s0, s1, s2, s3;
                xf2(acc[t][n][0], acc[t][n][1], s0, s1);
                xf2(acc[t][n][2], acc[t][n][3], s2, s3);
                colacc[n][0] += s0 + s2;
                colacc[n][1] += s1 + s3;
                int col = kbG + wk * 32 + n * 8 + tig * 2;
                __stcs((float2*)(Ag + (size_t)row0 * S + col), make_float2(s0, s1));
                __stcs((float2*)(Ag + (size_t)(row0 + 8) * S + col), make_float2(s2, s3));
            }
        }
    }

    // column-sum fold: reduce over grp lanes, stash per warp, fold wq pairs
#pragma unroll
    for (int n = 0; n < 4; n++)
#pragma unroll
        for (int h = 0; h < 2; h++) {
            float x = colacc[n][h];
            x += __shfl_xor_sync(0xffffffffu, x, 4);
            x += __shfl_xor_sync(0xffffffffu, x, 8);
            x += __shfl_xor_sync(0xffffffffu, x, 16);
            colacc[n][h] = x;
        }
    if (lane < 4) {
#pragma unroll
        for (int n = 0; n < 4; n++) {
            scr[wid * 32 + n * 8 + lane * 2]     = colacc[n][0];
            scr[wid * 32 + n * 8 + lane * 2 + 1] = colacc[n][1];
        }
    }
    __syncthreads();
    if (tid < 128) {
        int wkk = tid >> 5, c = tid & 31;
        g_NC[bh * S + kbG + wkk * 32 + c] = scr[wkk * 32 + c] + scr[(4 + wkk) * 32 + c];
    }
}

// ============================================================================
// Kernel 2: rc = rsqrt(N_C)
// ============================================================================
__global__ void k_prep() {
    int i = blockIdx.x * 256 + threadIdx.x;
    if (i < BH * S) g_RC[i] = rsqrtf(g_NC[i]);
}

// ============================================================================
// Kernel 3: rowsums. rinv[q] = 1 / sum_k s[q,k]*rc[k].
// ============================================================================
__global__ __launch_bounds__(256)
void k_rowsum(const float* __restrict__ attn) {
    const int bh = blockIdx.y;
    const int q0 = blockIdx.x * 64;
    const int w  = threadIdx.x >> 5;
    const int l  = threadIdx.x & 31;

    const float4* rc4 = (const float4*)(g_RC + bh * S);
    const float*  Ag  = attn + (size_t)bh * S * S;

    float acc[8];
#pragma unroll
    for (int r = 0; r < 8; r++) acc[r] = 0.f;
    const float4* row[8];
#pragma unroll
    for (int r = 0; r < 8; r++)
        row[r] = (const float4*)(Ag + (size_t)(q0 + w * 8 + r) * S);

#pragma unroll 2
    for (int step = 0; step < 16; step++) {
        int c = step * 32 + l;
        float4 rcv = __ldg(&rc4[c]);
#pragma unroll
        for (int r = 0; r < 8; r++) {
            float4 sv = __ldcs(&row[r][c]);
            acc[r] += sv.x * rcv.x + sv.y * rcv.y + sv.z * rcv.z + sv.w * rcv.w;
        }
    }
#pragma unroll
    for (int r = 0; r < 8; r++) {
#pragma unroll
        for (int off = 16; off; off >>= 1)
            acc[r] += __shfl_xor_sync(0xffffffffu, acc[r], off);
    }
    if (l == 0) {
#pragma unroll
        for (int r = 0; r < 8; r++)
            g_RS[bh * S + q0 + w * 8 + r] = 1.0f / acc[r];
    }
}

// ============================================================================
// Kernel 4: weights + AV via HMMA bf16x3. Block 256thr = 8 warps (4q x 2d).
// Tile 128q x 64d; k-chunks of 64. Warp: 32q x 32d.
// smem: Whi|Wlo [128][72], Vhi|Vlo [64][72].
// ============================================================================
#define WV_SMEM (2 * 128 * PADW * 2 + 2 * 64 * PADW * 2)

__global__ __launch_bounds__(256, 2)
void k_wav_mma(float* __restrict__ attn, const float* __restrict__ unused,
               float* __restrict__ Og_) {
    extern __shared__ char smc[];
    __nv_bfloat16* Whi = (__nv_bfloat16*)smc;
    __nv_bfloat16* Wlo = Whi + 128 * PADW;
    __nv_bfloat16* Vhi = Wlo + 128 * PADW;
    __nv_bfloat16* Vlo = Vhi + 64 * PADW;

    const int qb = blockIdx.x * 128, bh = blockIdx.y;
    const int tid = threadIdx.x, wid = tid >> 5, lane = tid & 31;
    const int wq = wid >> 1, wd = wid & 1;
    const int grp = lane >> 2, tig = lane & 3;
    const int r8 = lane & 7, ts = lane >> 3;

    float* Ag = attn + (size_t)bh * S * S;
    float* Og = Og_ + (size_t)bh * S * D;
    const __nv_bfloat16* VhiG = g_Vhi + (size_t)bh * S * D;
    const __nv_bfloat16* VloG = g_Vlo + (size_t)bh * S * D;
    const float* rcg = g_RC + bh * S;
    const float* rig = g_RS + bh * S;

    const u32 sWh = smem_u32(Whi), sWl = smem_u32(Wlo);
    const u32 sVh = smem_u32(Vhi), sVl = smem_u32(Vlo);
    // A frag (W, non-trans): row = wq*32 + t*16 + (ts&1)*8 + r8, col = ks*16 + (ts>>1)*8
    const u32 aOff = (u32)(((wq * 32 + (ts & 1) * 8 + r8) * PADW + (ts >> 1) * 8) * 2);
    // B frag (V, trans): k-row = ks*16 + (ts&1)*8 + r8, d = wd*32 + p*16 + ((ts>>1)&1)*8
    const u32 bOff = (u32)((((ts & 1) * 8 + r8) * PADW + wd * 32 + ((ts >> 1) & 1) * 8) * 2);

    float acc[2][4][4];
#pragma unroll
    for (int t = 0; t < 2; t++)
#pragma unroll
        for (int n = 0; n < 4; n++)
#pragma unroll
            for (int c = 0; c < 4; c++) acc[t][n][c] = 0.f;

    for (int cb = 0; cb < S; cb += 64) {
        __syncthreads();
        // stage W: load raw s, rescale, write final weights back, split bf16
#pragma unroll
        for (int i = 0; i < 8; i++) {
            int t = tid + 256 * i;           // 0..2047
            int m = t >> 4, c4 = t & 15;
            float* gp = Ag + (size_t)(qb + m) * S + cb + c4 * 4;
            float4 sv = __ldcs((const float4*)gp);
            float ri = __ldg(rig + qb + m);
            float4 rc = __ldg((const float4*)(rcg + cb + c4 * 4));
            float4 wv;
            wv.x = sv.x * rc.x * ri;
            wv.y = sv.y * rc.y * ri;
            wv.z = sv.z * rc.z * ri;
            wv.w = sv.w * rc.w * ri;
            __stcs((float4*)gp, wv);
            __nv_bfloat162 h01 = __floats2bfloat162_rn(wv.x, wv.y);
            __nv_bfloat162 h23 = __floats2bfloat162_rn(wv.z, wv.w);
            __nv_bfloat162 l01 = __floats2bfloat162_rn(wv.x - __bfloat162float(h01.x),
                                                       wv.y - __bfloat162float(h01.y));
            __nv_bfloat162 l23 = __floats2bfloat162_rn(wv.z - __bfloat162float(h23.x),
                                                       wv.w - __bfloat162float(h23.y));
            *(uint2*)(Whi + m * PADW + c4 * 4) =
                make_uint2(*(u32*)&h01, *(u32*)&h23);
            *(uint2*)(Wlo + m * PADW + c4 * 4) =
                make_uint2(*(u32*)&l01, *(u32*)&l23);
        }
        // stage V
#pragma unroll
        for (int i = 0; i < 2; i++) {
            int idx = tid + 256 * i, row = idx >> 3, c8 = idx & 7;
            *(uint4*)(Vhi + row * PADW + c8 * 8) = *(const uint4*)(VhiG + (size_t)(cb + row) * D + c8 * 8);
            *(uint4*)(Vlo + row * PADW + c8 * 8) = *(const uint4*)(VloG + (size_t)(cb + row) * D + c8 * 8);
        }
        __syncthreads();

#pragma unroll
        for (int ks = 0; ks < 4; ks++) {
            u32 bfh0[4], bfh1[4], bfl0[4], bfl1[4];
            ldm4t(sVh + bOff + ks * 2304, bfh0);
            ldm4t(sVh + bOff + 32 + ks * 2304, bfh1);
            ldm4t(sVl + bOff + ks * 2304, bfl0);
            ldm4t(sVl + bOff + 32 + ks * 2304, bfl1);
#pragma unroll
            for (int t = 0; t < 2; t++) {
                u32 ah[4], al[4];
                ldm4(sWh + aOff + t * 2304 + ks * 32, ah);
                ldm4(sWl + aOff + t * 2304 + ks * 32, al);
#pragma unroll
                for (int n = 0; n < 4; n++) {
                    const u32* bp = (n < 2) ? bfh0 : bfh1;
                    const u32* lp = (n < 2) ? bfl0 : bfl1;
                    int h = (n & 1) * 2;
                    mma_bf16(acc[t][n], ah, bp[h], bp[h + 1]);
                    mma_bf16(acc[t][n], ah, lp[h], lp[h + 1]);
                    mma_bf16(acc[t][n], al, bp[h], bp[h + 1]);
                }
            }
        }
    }

    // store O
#pragma unroll
    for (int t = 0; t < 2; t++) {
        int row0 = qb + wq * 32 + t * 16 + grp;
#pragma unroll
        for (int n = 0; n < 4; n++) {
            int col = wd * 32 + n * 8 + tig * 2;
            *(float2*)(Og + (size_t)row0 * D + col)       = make_float2(acc[t][n][0], acc[t][n][1]);
            *(float2*)(Og + (size_t)(row0 + 8) * D + col) = make_float2(acc[t][n][2], acc[t][n][3]);
        }
    }
}

// ============================================================================
extern "C" void kernel_launch(void* const* d_in, const int* in_sizes, int n_in,
                              void* d_out, int out_size) {
    const float* q = (const float*)d_in[0];
    const float* k = (const float*)d_in[1];
    const float* v = (const float*)d_in[2];
    // d_in[3] = attn_mask (all False) — no-op in reference.

    float* out  = (float*)d_out;
    float* O    = out;                       // [B,H,S,D]
    float* attn = out + (size_t)BH * S * D;  // [B,H,S,S]

    cudaFuncSetAttribute(k_scores_mma, cudaFuncAttributeMaxDynamicSharedMemorySize, SC_SMEM);
    cudaFuncSetAttribute(k_wav_mma,    cudaFuncAttributeMaxDynamicSharedMemorySize, WV_SMEM);

    dim3 gc((BH * S * D / 4 + 255) / 256, 3);
    k_convert<<<gc, 256>>>(q, k, v);

    dim3 g1(S / 128, BH);
    k_scores_mma<<<g1, 256, SC_SMEM>>>(attn);

    k_prep<<<(BH * S + 255) / 256, 256>>>();

    dim3 g3(S / 64, BH);
    k_rowsum<<<g3, 256>>>(attn);

    dim3 g4(S / 128, BH);
    k_wav_mma<<<g4, 256, WV_SMEM>>>(attn, nullptr, O);
}

// round 10
// speedup vs baseline: 2.1292x; 1.0509x over previous
#include <cuda_runtime.h>
#include <cuda_bf16.h>
#include <math.h>

#define S   2048
#define D   64
#define BH  32

typedef unsigned long long u64;
typedef unsigned int u32;

// scratch
__device__ float g_NC[BH * S];
__device__ float g_RC[BH * S];
__device__ float g_RS[BH * S];
__device__ __nv_bfloat16 g_Qhi[BH * S * D];
__device__ __nv_bfloat16 g_Qlo[BH * S * D];
__device__ __nv_bfloat16 g_Khi[BH * S * D];
__device__ __nv_bfloat16 g_Klo[BH * S * D];
__device__ __nv_bfloat16 g_Vhi[BH * S * D];
__device__ __nv_bfloat16 g_Vlo[BH * S * D];

// ---------- packed fp32x2 helpers ----------
__device__ __forceinline__ u64 pk2(float x, float y) {
    u64 r; asm("mov.b64 %0, {%1, %2};" : "=l"(r) : "f"(x), "f"(y)); return r;
}
__device__ __forceinline__ void upk2(u64 v, float &x, float &y) {
    asm("mov.b64 {%0, %1}, %2;" : "=f"(x), "=f"(y) : "l"(v));
}
__device__ __forceinline__ u64 fma2n(u64 a, u64 b, u64 c) {
    u64 d; asm("fma.rn.f32x2 %0, %1, %2, %3;" : "=l"(d) : "l"(a), "l"(b), "l"(c)); return d;
}
__device__ __forceinline__ u64 mul2(u64 a, u64 b) {
    u64 d; asm("mul.rn.f32x2 %0, %1, %2;" : "=l"(d) : "l"(a), "l"(b)); return d;
}
__device__ __forceinline__ u64 add2(u64 a, u64 b) {
    u64 d; asm("add.rn.f32x2 %0, %1, %2;" : "=l"(d) : "l"(a), "l"(b)); return d;
}

// s = exp(-acos(1-t)^2): acos(1-t)^2 = 2t*P(t)^2, P = deg-9 Taylor of acos(1-t)/sqrt(2t)
__device__ __forceinline__ void xf2(float x0, float x1, float &s0, float &s1) {
    const u64 ONE  = pk2(1.f, 1.f);
    const u64 NONE = pk2(-1.f, -1.f);
    u64 t = fma2n(pk2(x0, x1), NONE, ONE);
    u64 p = fma2n(pk2(1.9066e-5f, 1.9066e-5f), t, pk2(4.5125e-5f, 4.5125e-5f));
    p = fma2n(p, t, pk2(1.09101e-4f, 1.09101e-4f));
    p = fma2n(p, t, pk2(2.71137e-4f, 2.71137e-4f));
    p = fma2n(p, t, pk2(6.99129e-4f, 6.99129e-4f));
    p = fma2n(p, t, pk2(1.89887e-3f, 1.89887e-3f));
    p = fma2n(p, t, pk2(5.58036e-3f, 5.58036e-3f));
    p = fma2n(p, t, pk2(1.875e-2f, 1.875e-2f));
    p = fma2n(p, t, pk2(8.3333333e-2f, 8.3333333e-2f));
    p = fma2n(p, t, ONE);
    u64 phi = mul2(add2(t, t), mul2(p, p));
    float f0, f1; upk2(phi, f0, f1);
    s0 = __expf(-f0);
    s1 = __expf(-f1);
}

// ---------- mma / ldmatrix / cp.async helpers (legacy path, valid on plain sm_103) ----------
__device__ __forceinline__ u32 smem_u32(const void* p) {
    u32 a;
    asm("{ .reg .u64 t; cvta.to.shared.u64 t, %1; cvt.u32.u64 %0, t; }" : "=r"(a) : "l"(p));
    return a;
}
__device__ __forceinline__ void ldm4(u32 addr, u32 r[4]) {
    asm volatile("ldmatrix.sync.aligned.m8n8.x4.shared.b16 {%0,%1,%2,%3}, [%4];"
                 : "=r"(r[0]), "=r"(r[1]), "=r"(r[2]), "=r"(r[3]) : "r"(addr));
}
__device__ __forceinline__ void ldm4t(u32 addr, u32 r[4]) {
    asm volatile("ldmatrix.sync.aligned.m8n8.x4.trans.shared.b16 {%0,%1,%2,%3}, [%4];"
                 : "=r"(r[0]), "=r"(r[1]), "=r"(r[2]), "=r"(r[3]) : "r"(addr));
}
__device__ __forceinline__ void mma_bf16(float c[4], const u32 a[4], u32 b0, u32 b1) {
    asm volatile(
        "mma.sync.aligned.m16n8k16.row.col.f32.bf16.bf16.f32 "
        "{%0,%1,%2,%3}, {%4,%5,%6,%7}, {%8,%9}, {%0,%1,%2,%3};"
        : "+f"(c[0]), "+f"(c[1]), "+f"(c[2]), "+f"(c[3])
        : "r"(a[0]), "r"(a[1]), "r"(a[2]), "r"(a[3]), "r"(b0), "r"(b1));
}
__device__ __forceinline__ void cpa16(u32 dst, const void* src) {
    asm volatile("cp.async.cg.shared.global [%0], [%1], 16;" :: "r"(dst), "l"(src) : "memory");
}
#define CPA_COMMIT() asm volatile("cp.async.commit_group;" ::: "memory")
#define CPA_WAIT0()  asm volatile("cp.async.wait_group 0;" ::: "memory")

#define PADW 72   // bf16 row stride (144B = 16*9): ldmatrix conflict-free

// ============================================================================
// Kernel 0: fp32 -> bf16 hi/lo split for Q, K, V
// ============================================================================
__global__ void k_convert(const float* __restrict__ q, const float* __restrict__ k,
                          const float* __restrict__ v) {
    int i = blockIdx.x * 256 + threadIdx.x;
    const int n4 = BH * S * D / 4;
    if (i >= n4) return;
    const float4* src;
    __nv_bfloat16 *hi, *lo;
    if (blockIdx.y == 0)      { src = (const float4*)q; hi = g_Qhi; lo = g_Qlo; }
    else if (blockIdx.y == 1) { src = (const float4*)k; hi = g_Khi; lo = g_Klo; }
    else                      { src = (const float4*)v; hi = g_Vhi; lo = g_Vlo; }
    float4 w = src[i];
    __nv_bfloat16 hx = __float2bfloat16(w.x), hy = __float2bfloat16(w.y);
    __nv_bfloat16 hz = __float2bfloat16(w.z), hw = __float2bfloat16(w.w);
    ushort4 h, l;
    h.x = __bfloat16_as_ushort(hx); h.y = __bfloat16_as_ushort(hy);
    h.z = __bfloat16_as_ushort(hz); h.w = __bfloat16_as_ushort(hw);
    l.x = __bfloat16_as_ushort(__float2bfloat16(w.x - __bfloat162float(hx)));
    l.y = __bfloat16_as_ushort(__float2bfloat16(w.y - __bfloat162float(hy)));
    l.z = __bfloat16_as_ushort(__float2bfloat16(w.z - __bfloat162float(hz)));
    l.w = __bfloat16_as_ushort(__float2bfloat16(w.w - __bfloat162float(hw)));
    *(ushort4*)(hi + 4 * (size_t)i) = h;
    *(ushort4*)(lo + 4 * (size_t)i) = l;
}

// ============================================================================
// Kernel 1: scores via HMMA bf16x3, cp.async double-buffered A.
// Block 256thr = 8 warps (2q x 4k). Tile 128q x 128k; K resident; 16 q-tiles.
// smem bytes: Bhi 0 | Blo 18432 | A0hi 36864 | A0lo 55296 | A1hi 73728 |
//             A1lo 92160 | scr 110592 (1024B). total 111616.
// ============================================================================
#define TB 18432
#define SC_SMEM (6 * TB + 1024)

__global__ __launch_bounds__(256, 2)
void k_scores_mma(float* __restrict__ attn) {
    extern __shared__ char smc[];
    __nv_bfloat16* Bhi = (__nv_bfloat16*)smc;
    __nv_bfloat16* Blo = (__nv_bfloat16*)(smc + TB);
    float* scr = (float*)(smc + 6 * TB);
    const u32 sbase = smem_u32(smc);

    const int kbG = blockIdx.x * 128, bh = blockIdx.y;
    const int tid = threadIdx.x, wid = tid >> 5, lane = tid & 31;
    const int wq = wid >> 2, wk = wid & 3;
    const int grp = lane >> 2, tig = lane & 3;
    const int r8 = lane & 7, ts = lane >> 3;

    const __nv_bfloat16* QhiG = g_Qhi + (size_t)bh * S * D;
    const __nv_bfloat16* QloG = g_Qlo + (size_t)bh * S * D;
    const __nv_bfloat16* KhiG = g_Khi + (size_t)bh * S * D;
    const __nv_bfloat16* KloG = g_Klo + (size_t)bh * S * D;
    float* Ag = attn + (size_t)bh * S * S;

    // stage K (resident, regular loads)
#pragma unroll
    for (int i = 0; i < 4; i++) {
        int idx = tid + 256 * i, row = idx >> 3, c8 = idx & 7;
        *(uint4*)(Bhi + row * PADW + c8 * 8) = *(const uint4*)(KhiG + (size_t)(kbG + row) * D + c8 * 8);
        *(uint4*)(Blo + row * PADW + c8 * 8) = *(const uint4*)(KloG + (size_t)(kbG + row) * D + c8 * 8);
    }

    const u32 sBh = sbase, sBl = sbase + TB;
    const u32 aOff = (u32)(((wq * 64 + (ts & 1) * 8 + r8) * PADW + (ts >> 1) * 8) * 2);
    const u32 bOff = (u32)(((wk * 32 + ((ts >> 1) & 1) * 8 + r8) * PADW + (ts & 1) * 8) * 2);

    // cp.async staging of an A q-tile into buffer b
    auto stageA = [&](int qb, int b) {
        u32 dh = sbase + 2 * TB + (u32)b * 2 * TB;
        u32 dl = dh + TB;
#pragma unroll
        for (int i = 0; i < 4; i++) {
            int idx = tid + 256 * i, row = idx >> 3, c8 = idx & 7;
            u32 off = (u32)(row * (PADW * 2) + c8 * 16);
            cpa16(dh + off, QhiG + (size_t)(qb + row) * D + c8 * 8);
            cpa16(dl + off, QloG + (size_t)(qb + row) * D + c8 * 8);
        }
    };

    float colacc[4][2];
#pragma unroll
    for (int n = 0; n < 4; n++) { colacc[n][0] = 0.f; colacc[n][1] = 0.f; }

    stageA(0, 0);
    CPA_COMMIT();

    for (int it = 0; it < 16; it++) {
        const int qb = it * 128;
        CPA_WAIT0();
        __syncthreads();                 // A(it) visible; prior reads of buf[(it+1)&1] done
        if (it < 15) { stageA(qb + 128, (it + 1) & 1); CPA_COMMIT(); }

        const u32 sAh = sbase + 2 * TB + (u32)(it & 1) * 2 * TB;
        const u32 sAl = sAh + TB;

        float acc[4][4][4];
#pragma unroll
        for (int t = 0; t < 4; t++)
#pragma unroll
            for (int n = 0; n < 4; n++)
#pragma unroll
                for (int c = 0; c < 4; c++) acc[t][n][c] = 0.f;

#pragma unroll
        for (int ks = 0; ks < 4; ks++) {
            u32 bfh0[4], bfh1[4], bfl0[4], bfl1[4];
            ldm4(sBh + bOff + ks * 32, bfh0);
            ldm4(sBh + bOff + 2304 + ks * 32, bfh1);
            ldm4(sBl + bOff + ks * 32, bfl0);
            ldm4(sBl + bOff + 2304 + ks * 32, bfl1);
#pragma unroll
            for (int t = 0; t < 4; t++) {
                u32 ah[4], al[4];
                ldm4(sAh + aOff + t * 2304 + ks * 32, ah);
                ldm4(sAl + aOff + t * 2304 + ks * 32, al);
#pragma unroll
                for (int n = 0; n < 4; n++) {
                    const u32* bp = (n < 2) ? bfh0 : bfh1;
                    const u32* lp = (n < 2) ? bfl0 : bfl1;
                    int h = (n & 1) * 2;
                    mma_bf16(acc[t][n], ah, bp[h], bp[h + 1]);
                    mma_bf16(acc[t][n], ah, lp[h], lp[h + 1]);
                    mma_bf16(acc[t][n], al, bp[h], bp[h + 1]);
                }
            }
        }

        // epilogue: transform + store + colsum accumulate
#pragma unroll
        for (int t = 0; t < 4; t++) {
            int row0 = qb + wq * 64 + t * 16 + grp;
#pragma unroll
            for (int n = 0; n < 4; n++) {
                float s0, s1, s2, s3;
                xf2(acc[t][n][0], acc[t][n][1], s0, s1);
                xf2(acc[t][n][2], acc[t][n][3], s2, s3);
                colacc[n][0] += s0 + s2;
                colacc[n][1] += s1 + s3;
                int col = kbG + wk * 32 + n * 8 + tig * 2;
                __stcs((float2*)(Ag + (size_t)row0 * S + col), make_float2(s0, s1));
                __stcs((float2*)(Ag + (size_t)(row0 + 8) * S + col), make_float2(s2, s3));
            }
        }
    }

    // column-sum fold
#pragma unroll
    for (int n = 0; n < 4; n++)
#pragma unroll
        for (int h = 0; h < 2; h++) {
            float x = colacc[n][h];
            x += __shfl_xor_sync(0xffffffffu, x, 4);
            x += __shfl_xor_sync(0xffffffffu, x, 8);
            x += __shfl_xor_sync(0xffffffffu, x, 16);
            colacc[n][h] = x;
        }
    if (lane < 4) {
#pragma unroll
        for (int n = 0; n < 4; n++) {
            scr[wid * 32 + n * 8 + lane * 2]     = colacc[n][0];
            scr[wid * 32 + n * 8 + lane * 2 + 1] = colacc[n][1];
        }
    }
    __syncthreads();
    if (tid < 128) {
        int wkk = tid >> 5, c = tid & 31;
        g_NC[bh * S + kbG + wkk * 32 + c] = scr[wkk * 32 + c] + scr[(4 + wkk) * 32 + c];
    }
}

// ============================================================================
// Kernel 2: rc = rsqrt(N_C)
// ============================================================================
__global__ void k_prep() {
    int i = blockIdx.x * 256 + threadIdx.x;
    if (i < BH * S) g_RC[i] = rsqrtf(g_NC[i]);
}

// ============================================================================
// Kernel 3: rowsums. rinv[q] = 1 / sum_k s[q,k]*rc[k].
// ============================================================================
__global__ __launch_bounds__(256)
void k_rowsum(const float* __restrict__ attn) {
    const int bh = blockIdx.y;
    const int q0 = blockIdx.x * 64;
    const int w  = threadIdx.x >> 5;
    const int l  = threadIdx.x & 31;

    const float4* rc4 = (const float4*)(g_RC + bh * S);
    const float*  Ag  = attn + (size_t)bh * S * S;

    float acc[8];
#pragma unroll
    for (int r = 0; r < 8; r++) acc[r] = 0.f;
    const float4* row[8];
#pragma unroll
    for (int r = 0; r < 8; r++)
        row[r] = (const float4*)(Ag + (size_t)(q0 + w * 8 + r) * S);

#pragma unroll 2
    for (int step = 0; step < 16; step++) {
        int c = step * 32 + l;
        float4 rcv = __ldg(&rc4[c]);
#pragma unroll
        for (int r = 0; r < 8; r++) {
            float4 sv = __ldcs(&row[r][c]);
            acc[r] += sv.x * rcv.x + sv.y * rcv.y + sv.z * rcv.z + sv.w * rcv.w;
        }
    }
#pragma unroll
    for (int r = 0; r < 8; r++) {
#pragma unroll
        for (int off = 16; off; off >>= 1)
            acc[r] += __shfl_xor_sync(0xffffffffu, acc[r], off);
    }
    if (l == 0) {
#pragma unroll
        for (int r = 0; r < 8; r++)
            g_RS[bh * S + q0 + w * 8 + r] = 1.0f / acc[r];
    }
}

// ============================================================================
// Kernel 4: weights + AV via HMMA bf16x3, double-buffered pipeline.
// k-chunk 32; W via prefetched LDG -> regs -> STS; V via cp.async.
// Block 256thr = 8 warps (4q x 2d). Warp: 32q x 32d.
// smem bytes: W0hi 0 | W0lo 10240 | W1hi 20480 | W1lo 30720 |
//             V0hi 40960 | V0lo 45568 | V1hi 50176 | V1lo 54784. total 59392.
// W layout [128][40] bf16 (80B rows = 16*5); V layout [32][72] bf16.
// ============================================================================
#define PWW 40
#define WTB 10240
#define VTB 4608
#define WV_SMEM 59392
#define NI (S / 32)

__global__ __launch_bounds__(256, 2)
void k_wav_mma(float* __restrict__ attn, float* __restrict__ Og_) {
    extern __shared__ char smc[];
    const u32 sbase = smem_u32(smc);

    const int qb = blockIdx.x * 128, bh = blockIdx.y;
    const int tid = threadIdx.x, wid = tid >> 5, lane = tid & 31;
    const int wq = wid >> 1, wd = wid & 1;
    const int grp = lane >> 2, tig = lane & 3;
    const int r8 = lane & 7, ts = lane >> 3;
    const int c4 = tid & 7, m0 = tid >> 3;   // staging coords

    float* Ag = attn + (size_t)bh * S * S;
    float* Og = Og_ + (size_t)bh * S * D;
    const __nv_bfloat16* VhiG = g_Vhi + (size_t)bh * S * D;
    const __nv_bfloat16* VloG = g_Vlo + (size_t)bh * S * D;
    const float* rcg = g_RC + bh * S;
    const float* rig = g_RS + bh * S;

    const u32 aOff = (u32)(((wq * 32 + (ts & 1) * 8 + r8) * PWW + (ts >> 1) * 8) * 2);
    const u32 bOff = (u32)((((ts & 1) * 8 + r8) * PADW + wd * 32 + ((ts >> 1) & 1) * 8) * 2);

    float4 pf[2][4];
    float  pri[2][4];
    float4 prc[2];

    auto ldgW = [&](int it, int p) {
        int cb = it * 32;
        prc[p] = __ldg((const float4*)(rcg + cb + c4 * 4));
#pragma unroll
        for (int j = 0; j < 4; j++) {
            int m = m0 + 32 * j;
            pf[p][j]  = __ldcs((const float4*)(Ag + (size_t)(qb + m) * S + cb + c4 * 4));
            pri[p][j] = __ldg(rig + qb + m);
        }
    };
    auto cpaV = [&](int it, int b) {
        int cb = it * 32;
        u32 dh = sbase + 4 * WTB + (u32)b * 2 * VTB;
        u32 dl = dh + VTB;
        int row = tid >> 3, c8 = tid & 7;      // 256 thr = 32 rows x 8 chunks
        u32 off = (u32)(row * (PADW * 2) + c8 * 16);
        cpa16(dh + off, VhiG + (size_t)(cb + row) * D + c8 * 8);
        cpa16(dl + off, VloG + (size_t)(cb + row) * D + c8 * 8);
    };

    float acc[2][4][4];
#pragma unroll
    for (int t = 0; t < 2; t++)
#pragma unroll
        for (int n = 0; n < 4; n++)
#pragma unroll
            for (int c = 0; c < 4; c++) acc[t][n][c] = 0.f;

    // prologue
    ldgW(0, 0);
    cpaV(0, 0);
    CPA_COMMIT();

#pragma unroll 2
    for (int it = 0; it < NI; it++) {
        const int p = it & 1, pn = p ^ 1;
        const int cb = it * 32;

        // STS W(it) from prefetched regs: scale, write final weights back, split bf16
        {
            __nv_bfloat16* Whi = (__nv_bfloat16*)(smc + p * 2 * WTB);
            __nv_bfloat16* Wlo = (__nv_bfloat16*)(smc + p * 2 * WTB + WTB);
            float4 rc = prc[p];
#pragma unroll
            for (int j = 0; j < 4; j++) {
                int m = m0 + 32 * j;
                float4 sv = pf[p][j];
                float ri = pri[p][j];
                float4 wv;
                wv.x = sv.x * rc.x * ri;
                wv.y = sv.y * rc.y * ri;
                wv.z = sv.z * rc.z * ri;
                wv.w = sv.w * rc.w * ri;
                __stcs((float4*)(Ag + (size_t)(qb + m) * S + cb + c4 * 4), wv);
                __nv_bfloat162 h01 = __floats2bfloat162_rn(wv.x, wv.y);
                __nv_bfloat162 h23 = __floats2bfloat162_rn(wv.z, wv.w);
                __nv_bfloat162 l01 = __floats2bfloat162_rn(wv.x - __bfloat162float(h01.x),
                                                           wv.y - __bfloat162float(h01.y));
                __nv_bfloat162 l23 = __floats2bfloat162_rn(wv.z - __bfloat162float(h23.x),
                                                           wv.w - __bfloat162float(h23.y));
                *(uint2*)(Whi + m * PWW + c4 * 4) = make_uint2(*(u32*)&h01, *(u32*)&h23);
                *(uint2*)(Wlo + m * PWW + c4 * 4) = make_uint2(*(u32*)&l01, *(u32*)&l23);
            }
        }
        if (it + 1 < NI) ldgW(it + 1, pn);   // latency hidden by MMA below

        CPA_WAIT0();                          // V(it) landed
        __syncthreads();                      // W(it)/V(it) visible; old buffer reads done
        if (it + 1 < NI) { cpaV(it + 1, pn); CPA_COMMIT(); }

        // MMA on buffers p
        const u32 sWh = sbase + (u32)p * 2 * WTB;
        const u32 sWl = sWh + WTB;
        const u32 sVh = sbase + 4 * WTB + (u32)p * 2 * VTB;
        const u32 sVl = sVh + VTB;

#pragma unroll
        for (int ks = 0; ks < 2; ks++) {
            u32 bfh0[4], bfh1[4], bfl0[4], bfl1[4];
            ldm4t(sVh + bOff + ks * 2304, bfh0);
            ldm4t(sVh + bOff + 32 + ks * 2304, bfh1);
            ldm4t(sVl + bOff + ks * 2304, bfl0);
            ldm4t(sVl + bOff + 32 + ks * 2304, bfl1);
#pragma unroll
            for (int t = 0; t < 2; t++) {
                u32 ah[4], al[4];
                ldm4(sWh + aOff + t * 1280 + ks * 32, ah);
                ldm4(sWl + aOff + t * 1280 + ks * 32, al);
#pragma unroll
                for (int n = 0; n < 4; n++) {
                    const u32* bp = (n < 2) ? bfh0 : bfh1;
                    const u32* lp = (n < 2) ? bfl0 : bfl1;
                    int h = (n & 1) * 2;
                    mma_bf16(acc[t][n], ah, bp[h], bp[h + 1]);
                    mma_bf16(acc[t][n], ah, lp[h], lp[h + 1]);
                    mma_bf16(acc[t][n], al, bp[h], bp[h + 1]);
                }
            }
        }
    }

    // store O
#pragma unroll
    for (int t = 0; t < 2; t++) {
        int row0 = qb + wq * 32 + t * 16 + grp;
#pragma unroll
        for (int n = 0; n < 4; n++) {
            int col = wd * 32 + n * 8 + tig * 2;
            *(float2*)(Og + (size_t)row0 * D + col)       = make_float2(acc[t][n][0], acc[t][n][1]);
            *(float2*)(Og + (size_t)(row0 + 8) * D + col) = make_float2(acc[t][n][2], acc[t][n][3]);
        }
    }
}

// ============================================================================
extern "C" void kernel_launch(void* const* d_in, const int* in_sizes, int n_in,
                              void* d_out, int out_size) {
    const float* q = (const float*)d_in[0];
    const float* k = (const float*)d_in[1];
    const float* v = (const float*)d_in[2];
    // d_in[3] = attn_mask (all False) — no-op in reference.

    float* out  = (float*)d_out;
    float* O    = out;                       // [B,H,S,D]
    float* attn = out + (size_t)BH * S * D;  // [B,H,S,S]

    cudaFuncSetAttribute(k_scores_mma, cudaFuncAttributeMaxDynamicSharedMemorySize, SC_SMEM);
    cudaFuncSetAttribute(k_wav_mma,    cudaFuncAttributeMaxDynamicSharedMemorySize, WV_SMEM);

    dim3 gc((BH * S * D / 4 + 255) / 256, 3);
    k_convert<<<gc, 256>>>(q, k, v);

    dim3 g1(S / 128, BH);
    k_scores_mma<<<g1, 256, SC_SMEM>>>(attn);

    k_prep<<<(BH * S + 255) / 256, 256>>>();

    dim3 g3(S / 64, BH);
    k_rowsum<<<g3, 256>>>(attn);

    dim3 g4(S / 128, BH);
    k_wav_mma<<<g4, 256, WV_SMEM>>>(attn, O);
}

// round 14
// speedup vs baseline: 2.4457x; 1.1486x over previous
#include <cuda_runtime.h>
#include <cuda_bf16.h>
#include <math.h>

#define S   2048
#define D   64
#define BH  32

typedef unsigned long long u64;
typedef unsigned int u32;

// scratch
__device__ float g_NC[BH * S];
__device__ float g_RC[BH * S];
__device__ __nv_bfloat16 g_Qhi[BH * S * D];
__device__ __nv_bfloat16 g_Qlo[BH * S * D];
__device__ __nv_bfloat16 g_Khi[BH * S * D];
__device__ __nv_bfloat16 g_Klo[BH * S * D];
__device__ __nv_bfloat16 g_Vhi[BH * S * D];
__device__ __nv_bfloat16 g_Vlo[BH * S * D];

// ---------- packed fp32x2 helpers ----------
__device__ __forceinline__ u64 pk2(float x, float y) {
    u64 r; asm("mov.b64 %0, {%1, %2};" : "=l"(r) : "f"(x), "f"(y)); return r;
}
__device__ __forceinline__ void upk2(u64 v, float &x, float &y) {
    asm("mov.b64 {%0, %1}, %2;" : "=f"(x), "=f"(y) : "l"(v));
}
__device__ __forceinline__ u64 fma2n(u64 a, u64 b, u64 c) {
    u64 d; asm("fma.rn.f32x2 %0, %1, %2, %3;" : "=l"(d) : "l"(a), "l"(b), "l"(c)); return d;
}
__device__ __forceinline__ u64 mul2(u64 a, u64 b) {
    u64 d; asm("mul.rn.f32x2 %0, %1, %2;" : "=l"(d) : "l"(a), "l"(b)); return d;
}
__device__ __forceinline__ u64 add2(u64 a, u64 b) {
    u64 d; asm("add.rn.f32x2 %0, %1, %2;" : "=l"(d) : "l"(a), "l"(b)); return d;
}

// s = exp(-acos(1-t)^2): acos(1-t)^2 = 2t*P(t)^2, P = deg-9 Taylor of acos(1-t)/sqrt(2t)
__device__ __forceinline__ void xf2(float x0, float x1, float &s0, float &s1) {
    const u64 ONE  = pk2(1.f, 1.f);
    const u64 NONE = pk2(-1.f, -1.f);
    u64 t = fma2n(pk2(x0, x1), NONE, ONE);
    u64 p = fma2n(pk2(1.9066e-5f, 1.9066e-5f), t, pk2(4.5125e-5f, 4.5125e-5f));
    p = fma2n(p, t, pk2(1.09101e-4f, 1.09101e-4f));
    p = fma2n(p, t, pk2(2.71137e-4f, 2.71137e-4f));
    p = fma2n(p, t, pk2(6.99129e-4f, 6.99129e-4f));
    p = fma2n(p, t, pk2(1.89887e-3f, 1.89887e-3f));
    p = fma2n(p, t, pk2(5.58036e-3f, 5.58036e-3f));
    p = fma2n(p, t, pk2(1.875e-2f, 1.875e-2f));
    p = fma2n(p, t, pk2(8.3333333e-2f, 8.3333333e-2f));
    p = fma2n(p, t, ONE);
    u64 phi = mul2(add2(t, t), mul2(p, p));
    float f0, f1; upk2(phi, f0, f1);
    s0 = __expf(-f0);
    s1 = __expf(-f1);
}

// ---------- mma / ldmatrix / cp.async helpers ----------
__device__ __forceinline__ u32 smem_u32(const void* p) {
    u32 a;
    asm("{ .reg .u64 t; cvta.to.shared.u64 t, %1; cvt.u32.u64 %0, t; }" : "=r"(a) : "l"(p));
    return a;
}
__device__ __forceinline__ void ldm4(u32 addr, u32 r[4]) {
    asm volatile("ldmatrix.sync.aligned.m8n8.x4.shared.b16 {%0,%1,%2,%3}, [%4];"
                 : "=r"(r[0]), "=r"(r[1]), "=r"(r[2]), "=r"(r[3]) : "r"(addr));
}
__device__ __forceinline__ void ldm4t(u32 addr, u32 r[4]) {
    asm volatile("ldmatrix.sync.aligned.m8n8.x4.trans.shared.b16 {%0,%1,%2,%3}, [%4];"
                 : "=r"(r[0]), "=r"(r[1]), "=r"(r[2]), "=r"(r[3]) : "r"(addr));
}
__device__ __forceinline__ void mma_bf16(float c[4], const u32 a[4], u32 b0, u32 b1) {
    asm volatile(
        "mma.sync.aligned.m16n8k16.row.col.f32.bf16.bf16.f32 "
        "{%0,%1,%2,%3}, {%4,%5,%6,%7}, {%8,%9}, {%0,%1,%2,%3};"
        : "+f"(c[0]), "+f"(c[1]), "+f"(c[2]), "+f"(c[3])
        : "r"(a[0]), "r"(a[1]), "r"(a[2]), "r"(a[3]), "r"(b0), "r"(b1));
}
__device__ __forceinline__ void cpa16(u32 dst, const void* src) {
    asm volatile("cp.async.cg.shared.global [%0], [%1], 16;" :: "r"(dst), "l"(src) : "memory");
}
#define CPA_COMMIT() asm volatile("cp.async.commit_group;" ::: "memory")
#define CPA_WAIT0()  asm volatile("cp.async.wait_group 0;" ::: "memory")

#define PADW 72   // bf16 row stride (144B = 16*9): ldmatrix conflict-free

// ============================================================================
// Kernel 0: fp32 -> bf16 hi/lo split for Q, K, V
// ============================================================================
__global__ void k_convert(const float* __restrict__ q, const float* __restrict__ k,
                          const float* __restrict__ v) {
    int i = blockIdx.x * 256 + threadIdx.x;
    const int n4 = BH * S * D / 4;
    if (i >= n4) return;
    const float4* src;
    __nv_bfloat16 *hi, *lo;
    if (blockIdx.y == 0)      { src = (const float4*)q; hi = g_Qhi; lo = g_Qlo; }
    else if (blockIdx.y == 1) { src = (const float4*)k; hi = g_Khi; lo = g_Klo; }
    else                      { src = (const float4*)v; hi = g_Vhi; lo = g_Vlo; }
    float4 w = src[i];
    __nv_bfloat16 hx = __float2bfloat16(w.x), hy = __float2bfloat16(w.y);
    __nv_bfloat16 hz = __float2bfloat16(w.z), hw = __float2bfloat16(w.w);
    ushort4 h, l;
    h.x = __bfloat16_as_ushort(hx); h.y = __bfloat16_as_ushort(hy);
    h.z = __bfloat16_as_ushort(hz); h.w = __bfloat16_as_ushort(hw);
    l.x = __bfloat16_as_ushort(__float2bfloat16(w.x - __bfloat162float(hx)));
    l.y = __bfloat16_as_ushort(__float2bfloat16(w.y - __bfloat162float(hy)));
    l.z = __bfloat16_as_ushort(__float2bfloat16(w.z - __bfloat162float(hz)));
    l.w = __bfloat16_as_ushort(__float2bfloat16(w.w - __bfloat162float(hw)));
    *(ushort4*)(hi + 4 * (size_t)i) = h;
    *(ushort4*)(lo + 4 * (size_t)i) = l;
}

// ============================================================================
// Kernel 1: scores via HMMA bf16x3, cp.async double-buffered A. (unchanged)
// ============================================================================
#define TB 18432
#define SC_SMEM (6 * TB + 1024)

__global__ __launch_bounds__(256, 2)
void k_scores_mma(float* __restrict__ attn) {
    extern __shared__ char smc[];
    __nv_bfloat16* Bhi = (__nv_bfloat16*)smc;
    __nv_bfloat16* Blo = (__nv_bfloat16*)(smc + TB);
    float* scr = (float*)(smc + 6 * TB);
    const u32 sbase = smem_u32(smc);

    const int kbG = blockIdx.x * 128, bh = blockIdx.y;
    const int tid = threadIdx.x, wid = tid >> 5, lane = tid & 31;
    const int wq = wid >> 2, wk = wid & 3;
    const int grp = lane >> 2, tig = lane & 3;
    const int r8 = lane & 7, ts = lane >> 3;

    const __nv_bfloat16* QhiG = g_Qhi + (size_t)bh * S * D;
    const __nv_bfloat16* QloG = g_Qlo + (size_t)bh * S * D;
    const __nv_bfloat16* KhiG = g_Khi + (size_t)bh * S * D;
    const __nv_bfloat16* KloG = g_Klo + (size_t)bh * S * D;
    float* Ag = attn + (size_t)bh * S * S;

#pragma unroll
    for (int i = 0; i < 4; i++) {
        int idx = tid + 256 * i, row = idx >> 3, c8 = idx & 7;
        *(uint4*)(Bhi + row * PADW + c8 * 8) = *(const uint4*)(KhiG + (size_t)(kbG + row) * D + c8 * 8);
        *(uint4*)(Blo + row * PADW + c8 * 8) = *(const uint4*)(KloG + (size_t)(kbG + row) * D + c8 * 8);
    }

    const u32 sBh = sbase, sBl = sbase + TB;
    const u32 aOff = (u32)(((wq * 64 + (ts & 1) * 8 + r8) * PADW + (ts >> 1) * 8) * 2);
    const u32 bOff = (u32)(((wk * 32 + ((ts >> 1) & 1) * 8 + r8) * PADW + (ts & 1) * 8) * 2);

    auto stageA = [&](int qb, int b) {
        u32 dh = sbase + 2 * TB + (u32)b * 2 * TB;
        u32 dl = dh + TB;
#pragma unroll
        for (int i = 0; i < 4; i++) {
            int idx = tid + 256 * i, row = idx >> 3, c8 = idx & 7;
            u32 off = (u32)(row * (PADW * 2) + c8 * 16);
            cpa16(dh + off, QhiG + (size_t)(qb + row) * D + c8 * 8);
            cpa16(dl + off, QloG + (size_t)(qb + row) * D + c8 * 8);
        }
    };

    float colacc[4][2];
#pragma unroll
    for (int n = 0; n < 4; n++) { colacc[n][0] = 0.f; colacc[n][1] = 0.f; }

    stageA(0, 0);
    CPA_COMMIT();

    for (int it = 0; it < 16; it++) {
        const int qb = it * 128;
        CPA_WAIT0();
        __syncthreads();
        if (it < 15) { stageA(qb + 128, (it + 1) & 1); CPA_COMMIT(); }

        const u32 sAh = sbase + 2 * TB + (u32)(it & 1) * 2 * TB;
        const u32 sAl = sAh + TB;

        float acc[4][4][4];
#pragma unroll
        for (int t = 0; t < 4; t++)
#pragma unroll
            for (int n = 0; n < 4; n++)
#pragma unroll
                for (int c = 0; c < 4; c++) acc[t][n][c] = 0.f;

#pragma unroll
        for (int ks = 0; ks < 4; ks++) {
            u32 bfh0[4], bfh1[4], bfl0[4], bfl1[4];
            ldm4(sBh + bOff + ks * 32, bfh0);
            ldm4(sBh + bOff + 2304 + ks * 32, bfh1);
            ldm4(sBl + bOff + ks * 32, bfl0);
            ldm4(sBl + bOff + 2304 + ks * 32, bfl1);
#pragma unroll
            for (int t = 0; t < 4; t++) {
                u32 ah[4], al[4];
                ldm4(sAh + aOff + t * 2304 + ks * 32, ah);
                ldm4(sAl + aOff + t * 2304 + ks * 32, al);
#pragma unroll
                for (int n = 0; n < 4; n++) {
                    const u32* bp = (n < 2) ? bfh0 : bfh1;
                    const u32* lp = (n < 2) ? bfl0 : bfl1;
                    int h = (n & 1) * 2;
                    mma_bf16(acc[t][n], ah, bp[h], bp[h + 1]);
                    mma_bf16(acc[t][n], ah, lp[h], lp[h + 1]);
                    mma_bf16(acc[t][n], al, bp[h], bp[h + 1]);
                }
            }
        }

#pragma unroll
        for (int t = 0; t < 4; t++) {
            int row0 = qb + wq * 64 + t * 16 + grp;
#pragma unroll
            for (int n = 0; n < 4; n++) {
                float s0, s1, s2, s3;
                xf2(acc[t][n][0], acc[t][n][1], s0, s1);
                xf2(acc[t][n][2], acc[t][n][3], s2, s3);
                colacc[n][0] += s0 + s2;
                colacc[n][1] += s1 + s3;
                int col = kbG + wk * 32 + n * 8 + tig * 2;
                __stcs((float2*)(Ag + (size_t)row0 * S + col), make_float2(s0, s1));
                __stcs((float2*)(Ag + (size_t)(row0 + 8) * S + col), make_float2(s2, s3));
            }
        }
    }

#pragma unroll
    for (int n = 0; n < 4; n++)
#pragma unroll
        for (int h = 0; h < 2; h++) {
            float x = colacc[n][h];
            x += __shfl_xor_sync(0xffffffffu, x, 4);
            x += __shfl_xor_sync(0xffffffffu, x, 8);
            x += __shfl_xor_sync(0xffffffffu, x, 16);
            colacc[n][h] = x;
        }
    if (lane < 4) {
#pragma unroll
        for (int n = 0; n < 4; n++) {
            scr[wid * 32 + n * 8 + lane * 2]     = colacc[n][0];
            scr[wid * 32 + n * 8 + lane * 2 + 1] = colacc[n][1];
        }
    }
    __syncthreads();
    if (tid < 128) {
        int wkk = tid >> 5, c = tid & 31;
        g_NC[bh * S + kbG + wkk * 32 + c] = scr[wkk * 32 + c] + scr[(4 + wkk) * 32 + c];
    }
}

// ============================================================================
// Kernel 2: rc = rsqrt(N_C)
// ============================================================================
__global__ void k_prep() {
    int i = blockIdx.x * 256 + threadIdx.x;
    if (i < BH * S) g_RC[i] = rsqrtf(g_NC[i]);
}

// ============================================================================
// Kernel 3: rowsum + in-place finalize. Per warp: 8 rows. Pass A: rowsum of
// s*rc (full bfly -> rinv in all lanes). Pass B: w = s*rc*rinv written back.
// No smem, no barriers. Second read is L2-assisted.
// ============================================================================
__global__ __launch_bounds__(256)
void k_rowscale(float* __restrict__ attn) {
    const int bh = blockIdx.y;
    const int q0 = blockIdx.x * 64;
    const int w  = threadIdx.x >> 5;
    const int l  = threadIdx.x & 31;

    const float4* rc4 = (const float4*)(g_RC + bh * S);
    float* Ag = attn + (size_t)bh * S * S;

    float4* row[8];
#pragma unroll
    for (int r = 0; r < 8; r++)
        row[r] = (float4*)(Ag + (size_t)(q0 + w * 8 + r) * S);

    float acc[8];
#pragma unroll
    for (int r = 0; r < 8; r++) acc[r] = 0.f;

#pragma unroll 2
    for (int step = 0; step < 16; step++) {
        int c = step * 32 + l;
        float4 rcv = __ldg(&rc4[c]);
#pragma unroll
        for (int r = 0; r < 8; r++) {
            float4 sv = __ldg(&row[r][c]);
            acc[r] += sv.x * rcv.x + sv.y * rcv.y + sv.z * rcv.z + sv.w * rcv.w;
        }
    }
    float ri[8];
#pragma unroll
    for (int r = 0; r < 8; r++) {
#pragma unroll
        for (int off = 16; off; off >>= 1)
            acc[r] += __shfl_xor_sync(0xffffffffu, acc[r], off);
        ri[r] = 1.0f / acc[r];
    }

    // pass B: finalize in place
#pragma unroll 2
    for (int step = 0; step < 16; step++) {
        int c = step * 32 + l;
        float4 rcv = __ldg(&rc4[c]);
#pragma unroll
        for (int r = 0; r < 8; r++) {
            float4 sv = __ldg(&row[r][c]);
            float4 wv;
            wv.x = sv.x * rcv.x * ri[r];
            wv.y = sv.y * rcv.y * ri[r];
            wv.z = sv.z * rcv.z * ri[r];
            wv.w = sv.w * rcv.w * ri[r];
            __stcs(&row[r][c], wv);
        }
    }
}

// ============================================================================
// Kernel 4: AV via HMMA bf16x3, double-buffered. Reads FINAL weights
// (no scaling, no attn write). k-chunk 32.
// smem: W0hi 0 | W0lo 10240 | W1hi 20480 | W1lo 30720 |
//       V0hi 40960 | V0lo 45568 | V1hi 50176 | V1lo 54784. total 59392.
// ============================================================================
#define PWW 40
#define WTB 10240
#define VTB 4608
#define WV_SMEM 59392
#define NI (S / 32)

__global__ __launch_bounds__(256, 2)
void k_wav_mma(const float* __restrict__ attn, float* __restrict__ Og_) {
    extern __shared__ char smc[];
    const u32 sbase = smem_u32(smc);

    const int qb = blockIdx.x * 128, bh = blockIdx.y;
    const int tid = threadIdx.x, wid = tid >> 5, lane = tid & 31;
    const int wq = wid >> 1, wd = wid & 1;
    const int grp = lane >> 2, tig = lane & 3;
    const int r8 = lane & 7, ts = lane >> 3;
    const int c4 = tid & 7, m0 = tid >> 3;

    const float* Ag = attn + (size_t)bh * S * S;
    float* Og = Og_ + (size_t)bh * S * D;
    const __nv_bfloat16* VhiG = g_Vhi + (size_t)bh * S * D;
    const __nv_bfloat16* VloG = g_Vlo + (size_t)bh * S * D;

    const u32 aOff = (u32)(((wq * 32 + (ts & 1) * 8 + r8) * PWW + (ts >> 1) * 8) * 2);
    const u32 bOff = (u32)((((ts & 1) * 8 + r8) * PADW + wd * 32 + ((ts >> 1) & 1) * 8) * 2);

    float4 pf[2][4];

    auto ldgW = [&](int it, int p) {
        int cb = it * 32;
#pragma unroll
        for (int j = 0; j < 4; j++) {
            int m = m0 + 32 * j;
            pf[p][j] = __ldcs((const float4*)(Ag + (size_t)(qb + m) * S + cb + c4 * 4));
        }
    };
    auto cpaV = [&](int it, int b) {
        int cb = it * 32;
        u32 dh = sbase + 4 * WTB + (u32)b * 2 * VTB;
        u32 dl = dh + VTB;
        int row = tid >> 3, c8 = tid & 7;
        u32 off = (u32)(row * (PADW * 2) + c8 * 16);
        cpa16(dh + off, VhiG + (size_t)(cb + row) * D + c8 * 8);
        cpa16(dl + off, VloG + (size_t)(cb + row) * D + c8 * 8);
    };

    float acc[2][4][4];
#pragma unroll
    for (int t = 0; t < 2; t++)
#pragma unroll
        for (int n = 0; n < 4; n++)
#pragma unroll
            for (int c = 0; c < 4; c++) acc[t][n][c] = 0.f;

    ldgW(0, 0);
    cpaV(0, 0);
    CPA_COMMIT();

#pragma unroll 2
    for (int it = 0; it < NI; it++) {
        const int p = it & 1, pn = p ^ 1;

        // STS W(it) from prefetched regs: bf16 hi/lo split only
        {
            __nv_bfloat16* Whi = (__nv_bfloat16*)(smc + p * 2 * WTB);
            __nv_bfloat16* Wlo = (__nv_bfloat16*)(smc + p * 2 * WTB + WTB);
#pragma unroll
            for (int j = 0; j < 4; j++) {
                int m = m0 + 32 * j;
                float4 wv = pf[p][j];
                __nv_bfloat162 h01 = __floats2bfloat162_rn(wv.x, wv.y);
                __nv_bfloat162 h23 = __floats2bfloat162_rn(wv.z, wv.w);
                __nv_bfloat162 l01 = __floats2bfloat162_rn(wv.x - __bfloat162float(h01.x),
                                                           wv.y - __bfloat162float(h01.y));
                __nv_bfloat162 l23 = __floats2bfloat162_rn(wv.z - __bfloat162float(h23.x),
                                                           wv.w - __bfloat162float(h23.y));
                *(uint2*)(Whi + m * PWW + c4 * 4) = make_uint2(*(u32*)&h01, *(u32*)&h23);
                *(uint2*)(Wlo + m * PWW + c4 * 4) = make_uint2(*(u32*)&l01, *(u32*)&l23);
            }
        }
        if (it + 1 < NI) ldgW(it + 1, pn);

        CPA_WAIT0();
        __syncthreads();
        if (it + 1 < NI) { cpaV(it + 1, pn); CPA_COMMIT(); }

        const u32 sWh = sbase + (u32)p * 2 * WTB;
        const u32 sWl = sWh + WTB;
        const u32 sVh = sbase + 4 * WTB + (u32)p * 2 * VTB;
        const u32 sVl = sVh + VTB;

#pragma unroll
        for (int ks = 0; ks < 2; ks++) {
            u32 bfh0[4], bfh1[4], bfl0[4], bfl1[4];
            ldm4t(sVh + bOff + ks * 2304, bfh0);
            ldm4t(sVh + bOff + 32 + ks * 2304, bfh1);
            ldm4t(sVl + bOff + ks * 2304, bfl0);
            ldm4t(sVl + bOff + 32 + ks * 2304, bfl1);
#pragma unroll
            for (int t = 0; t < 2; t++) {
                u32 ah[4], al[4];
                ldm4(sWh + aOff + t * 1280 + ks * 32, ah);
                ldm4(sWl + aOff + t * 1280 + ks * 32, al);
#pragma unroll
                for (int n = 0; n < 4; n++) {
                    const u32* bp = (n < 2) ? bfh0 : bfh1;
                    const u32* lp = (n < 2) ? bfl0 : bfl1;
                    int h = (n & 1) * 2;
                    mma_bf16(acc[t][n], ah, bp[h], bp[h + 1]);
                    mma_bf16(acc[t][n], ah, lp[h], lp[h + 1]);
                    mma_bf16(acc[t][n], al, bp[h], bp[h + 1]);
                }
            }
        }
    }

    // store O
#pragma unroll
    for (int t = 0; t < 2; t++) {
        int row0 = qb + wq * 32 + t * 16 + grp;
#pragma unroll
        for (int n = 0; n < 4; n++) {
            int col = wd * 32 + n * 8 + tig * 2;
            *(float2*)(Og + (size_t)row0 * D + col)       = make_float2(acc[t][n][0], acc[t][n][1]);
            *(float2*)(Og + (size_t)(row0 + 8) * D + col) = make_float2(acc[t][n][2], acc[t][n][3]);
        }
    }
}

// ============================================================================
extern "C" void kernel_launch(void* const* d_in, const int* in_sizes, int n_in,
                              void* d_out, int out_size) {
    const float* q = (const float*)d_in[0];
    const float* k = (const float*)d_in[1];
    const float* v = (const float*)d_in[2];
    // d_in[3] = attn_mask (all False) — no-op in reference.

    float* out  = (float*)d_out;
    float* O    = out;                       // [B,H,S,D]
    float* attn = out + (size_t)BH * S * D;  // [B,H,S,S]

    cudaFuncSetAttribute(k_scores_mma, cudaFuncAttributeMaxDynamicSharedMemorySize, SC_SMEM);
    cudaFuncSetAttribute(k_wav_mma,    cudaFuncAttributeMaxDynamicSharedMemorySize, WV_SMEM);

    dim3 gc((BH * S * D / 4 + 255) / 256, 3);
    k_convert<<<gc, 256>>>(q, k, v);

    dim3 g1(S / 128, BH);
    k_scores_mma<<<g1, 256, SC_SMEM>>>(attn);

    k_prep<<<(BH * S + 255) / 256, 256>>>();

    dim3 g3(S / 64, BH);
    k_rowscale<<<g3, 256>>>(attn);

    dim3 g4(S / 128, BH);
    k_wav_mma<<<g4, 256, WV_SMEM>>>(attn, O);
}

// round 16
// speedup vs baseline: 2.7831x; 1.1380x over previous
#include <cuda_runtime.h>
#include <cuda_bf16.h>
#include <math.h>

#define S   2048
#define D   64
#define BH  32

typedef unsigned long long u64;
typedef unsigned int u32;

// scratch
__device__ float g_NC[BH * S];
__device__ float g_RC[BH * S];
__device__ __nv_bfloat16 g_Qhi[BH * S * D];
__device__ __nv_bfloat16 g_Qlo[BH * S * D];
__device__ __nv_bfloat16 g_Khi[BH * S * D];
__device__ __nv_bfloat16 g_Klo[BH * S * D];
__device__ __nv_bfloat16 g_Vhi[BH * S * D];
__device__ __nv_bfloat16 g_Vlo[BH * S * D];

// ---------- packed fp32x2 helpers ----------
__device__ __forceinline__ u64 pk2(float x, float y) {
    u64 r; asm("mov.b64 %0, {%1, %2};" : "=l"(r) : "f"(x), "f"(y)); return r;
}
__device__ __forceinline__ void upk2(u64 v, float &x, float &y) {
    asm("mov.b64 {%0, %1}, %2;" : "=f"(x), "=f"(y) : "l"(v));
}
__device__ __forceinline__ u64 fma2n(u64 a, u64 b, u64 c) {
    u64 d; asm("fma.rn.f32x2 %0, %1, %2, %3;" : "=l"(d) : "l"(a), "l"(b), "l"(c)); return d;
}
__device__ __forceinline__ u64 mul2(u64 a, u64 b) {
    u64 d; asm("mul.rn.f32x2 %0, %1, %2;" : "=l"(d) : "l"(a), "l"(b)); return d;
}
__device__ __forceinline__ u64 add2(u64 a, u64 b) {
    u64 d; asm("add.rn.f32x2 %0, %1, %2;" : "=l"(d) : "l"(a), "l"(b)); return d;
}

// s = exp(-acos(1-t)^2): acos(1-t)^2 = 2t*P(t)^2, P = deg-9 Taylor of acos(1-t)/sqrt(2t)
__device__ __forceinline__ void xf2(float x0, float x1, float &s0, float &s1) {
    const u64 ONE  = pk2(1.f, 1.f);
    const u64 NONE = pk2(-1.f, -1.f);
    u64 t = fma2n(pk2(x0, x1), NONE, ONE);
    u64 p = fma2n(pk2(1.9066e-5f, 1.9066e-5f), t, pk2(4.5125e-5f, 4.5125e-5f));
    p = fma2n(p, t, pk2(1.09101e-4f, 1.09101e-4f));
    p = fma2n(p, t, pk2(2.71137e-4f, 2.71137e-4f));
    p = fma2n(p, t, pk2(6.99129e-4f, 6.99129e-4f));
    p = fma2n(p, t, pk2(1.89887e-3f, 1.89887e-3f));
    p = fma2n(p, t, pk2(5.58036e-3f, 5.58036e-3f));
    p = fma2n(p, t, pk2(1.875e-2f, 1.875e-2f));
    p = fma2n(p, t, pk2(8.3333333e-2f, 8.3333333e-2f));
    p = fma2n(p, t, ONE);
    u64 phi = mul2(add2(t, t), mul2(p, p));
    float f0, f1; upk2(phi, f0, f1);
    s0 = __expf(-f0);
    s1 = __expf(-f1);
}

// ---------- mma / ldmatrix / cp.async helpers ----------
__device__ __forceinline__ u32 smem_u32(const void* p) {
    u32 a;
    asm("{ .reg .u64 t; cvta.to.shared.u64 t, %1; cvt.u32.u64 %0, t; }" : "=r"(a) : "l"(p));
    return a;
}
__device__ __forceinline__ void ldm4(u32 addr, u32 r[4]) {
    asm volatile("ldmatrix.sync.aligned.m8n8.x4.shared.b16 {%0,%1,%2,%3}, [%4];"
                 : "=r"(r[0]), "=r"(r[1]), "=r"(r[2]), "=r"(r[3]) : "r"(addr));
}
__device__ __forceinline__ void ldm4t(u32 addr, u32 r[4]) {
    asm volatile("ldmatrix.sync.aligned.m8n8.x4.trans.shared.b16 {%0,%1,%2,%3}, [%4];"
                 : "=r"(r[0]), "=r"(r[1]), "=r"(r[2]), "=r"(r[3]) : "r"(addr));
}
__device__ __forceinline__ void mma_bf16(float c[4], const u32 a[4], u32 b0, u32 b1) {
    asm volatile(
        "mma.sync.aligned.m16n8k16.row.col.f32.bf16.bf16.f32 "
        "{%0,%1,%2,%3}, {%4,%5,%6,%7}, {%8,%9}, {%0,%1,%2,%3};"
        : "+f"(c[0]), "+f"(c[1]), "+f"(c[2]), "+f"(c[3])
        : "r"(a[0]), "r"(a[1]), "r"(a[2]), "r"(a[3]), "r"(b0), "r"(b1));
}
__device__ __forceinline__ void cpa16(u32 dst, const void* src) {
    asm volatile("cp.async.cg.shared.global [%0], [%1], 16;" :: "r"(dst), "l"(src) : "memory");
}
#define CPA_COMMIT() asm volatile("cp.async.commit_group;" ::: "memory")
#define CPA_WAIT0()  asm volatile("cp.async.wait_group 0;" ::: "memory")

#define PADW 72   // bf16 row stride (144B = 16*9): ldmatrix conflict-free

// ============================================================================
// Kernel 0: fp32 -> bf16 hi/lo split for Q, K, V
// ============================================================================
__global__ void k_convert(const float* __restrict__ q, const float* __restrict__ k,
                          const float* __restrict__ v) {
    int i = blockIdx.x * 256 + threadIdx.x;
    const int n4 = BH * S * D / 4;
    if (i >= n4) return;
    const float4* src;
    __nv_bfloat16 *hi, *lo;
    if (blockIdx.y == 0)      { src = (const float4*)q; hi = g_Qhi; lo = g_Qlo; }
    else if (blockIdx.y == 1) { src = (const float4*)k; hi = g_Khi; lo = g_Klo; }
    else                      { src = (const float4*)v; hi = g_Vhi; lo = g_Vlo; }
    float4 w = src[i];
    __nv_bfloat16 hx = __float2bfloat16(w.x), hy = __float2bfloat16(w.y);
    __nv_bfloat16 hz = __float2bfloat16(w.z), hw = __float2bfloat16(w.w);
    ushort4 h, l;
    h.x = __bfloat16_as_ushort(hx); h.y = __bfloat16_as_ushort(hy);
    h.z = __bfloat16_as_ushort(hz); h.w = __bfloat16_as_ushort(hw);
    l.x = __bfloat16_as_ushort(__float2bfloat16(w.x - __bfloat162float(hx)));
    l.y = __bfloat16_as_ushort(__float2bfloat16(w.y - __bfloat162float(hy)));
    l.z = __bfloat16_as_ushort(__float2bfloat16(w.z - __bfloat162float(hz)));
    l.w = __bfloat16_as_ushort(__float2bfloat16(w.w - __bfloat162float(hw)));
    *(ushort4*)(hi + 4 * (size_t)i) = h;
    *(ushort4*)(lo + 4 * (size_t)i) = l;
}

// ============================================================================
// Kernel 1: scores via HMMA bf16x3, cp.async double-buffered A. (unchanged)
// ============================================================================
#define TB 18432
#define SC_SMEM (6 * TB + 1024)

__global__ __launch_bounds__(256, 2)
void k_scores_mma(float* __restrict__ attn) {
    extern __shared__ char smc[];
    __nv_bfloat16* Bhi = (__nv_bfloat16*)smc;
    __nv_bfloat16* Blo = (__nv_bfloat16*)(smc + TB);
    float* scr = (float*)(smc + 6 * TB);
    const u32 sbase = smem_u32(smc);

    const int kbG = blockIdx.x * 128, bh = blockIdx.y;
    const int tid = threadIdx.x, wid = tid >> 5, lane = tid & 31;
    const int wq = wid >> 2, wk = wid & 3;
    const int grp = lane >> 2, tig = lane & 3;
    const int r8 = lane & 7, ts = lane >> 3;

    const __nv_bfloat16* QhiG = g_Qhi + (size_t)bh * S * D;
    const __nv_bfloat16* QloG = g_Qlo + (size_t)bh * S * D;
    const __nv_bfloat16* KhiG = g_Khi + (size_t)bh * S * D;
    const __nv_bfloat16* KloG = g_Klo + (size_t)bh * S * D;
    float* Ag = attn + (size_t)bh * S * S;

#pragma unroll
    for (int i = 0; i < 4; i++) {
        int idx = tid + 256 * i, row = idx >> 3, c8 = idx & 7;
        *(uint4*)(Bhi + row * PADW + c8 * 8) = *(const uint4*)(KhiG + (size_t)(kbG + row) * D + c8 * 8);
        *(uint4*)(Blo + row * PADW + c8 * 8) = *(const uint4*)(KloG + (size_t)(kbG + row) * D + c8 * 8);
    }

    const u32 sBh = sbase, sBl = sbase + TB;
    const u32 aOff = (u32)(((wq * 64 + (ts & 1) * 8 + r8) * PADW + (ts >> 1) * 8) * 2);
    const u32 bOff = (u32)(((wk * 32 + ((ts >> 1) & 1) * 8 + r8) * PADW + (ts & 1) * 8) * 2);

    auto stageA = [&](int qb, int b) {
        u32 dh = sbase + 2 * TB + (u32)b * 2 * TB;
        u32 dl = dh + TB;
#pragma unroll
        for (int i = 0; i < 4; i++) {
            int idx = tid + 256 * i, row = idx >> 3, c8 = idx & 7;
            u32 off = (u32)(row * (PADW * 2) + c8 * 16);
            cpa16(dh + off, QhiG + (size_t)(qb + row) * D + c8 * 8);
            cpa16(dl + off, QloG + (size_t)(qb + row) * D + c8 * 8);
        }
    };

    float colacc[4][2];
#pragma unroll
    for (int n = 0; n < 4; n++) { colacc[n][0] = 0.f; colacc[n][1] = 0.f; }

    stageA(0, 0);
    CPA_COMMIT();

    for (int it = 0; it < 16; it++) {
        const int qb = it * 128;
        CPA_WAIT0();
        __syncthreads();
        if (it < 15) { stageA(qb + 128, (it + 1) & 1); CPA_COMMIT(); }

        const u32 sAh = sbase + 2 * TB + (u32)(it & 1) * 2 * TB;
        const u32 sAl = sAh + TB;

        float acc[4][4][4];
#pragma unroll
        for (int t = 0; t < 4; t++)
#pragma unroll
            for (int n = 0; n < 4; n++)
#pragma unroll
                for (int c = 0; c < 4; c++) acc[t][n][c] = 0.f;

#pragma unroll
        for (int ks = 0; ks < 4; ks++) {
            u32 bfh0[4], bfh1[4], bfl0[4], bfl1[4];
            ldm4(sBh + bOff + ks * 32, bfh0);
            ldm4(sBh + bOff + 2304 + ks * 32, bfh1);
            ldm4(sBl + bOff + ks * 32, bfl0);
            ldm4(sBl + bOff + 2304 + ks * 32, bfl1);
#pragma unroll
            for (int t = 0; t < 4; t++) {
                u32 ah[4], al[4];
                ldm4(sAh + aOff + t * 2304 + ks * 32, ah);
                ldm4(sAl + aOff + t * 2304 + ks * 32, al);
#pragma unroll
                for (int n = 0; n < 4; n++) {
                    const u32* bp = (n < 2) ? bfh0 : bfh1;
                    const u32* lp = (n < 2) ? bfl0 : bfl1;
                    int h = (n & 1) * 2;
                    mma_bf16(acc[t][n], ah, bp[h], bp[h + 1]);
                    mma_bf16(acc[t][n], ah, lp[h], lp[h + 1]);
                    mma_bf16(acc[t][n], al, bp[h], bp[h + 1]);
                }
            }
        }

#pragma unroll
        for (int t = 0; t < 4; t++) {
            int row0 = qb + wq * 64 + t * 16 + grp;
#pragma unroll
            for (int n = 0; n < 4; n++) {
                float s0, s1, s2, s3;
                xf2(acc[t][n][0], acc[t][n][1], s0, s1);
                xf2(acc[t][n][2], acc[t][n][3], s2, s3);
                colacc[n][0] += s0 + s2;
                colacc[n][1] += s1 + s3;
                int col = kbG + wk * 32 + n * 8 + tig * 2;
                __stcs((float2*)(Ag + (size_t)row0 * S + col), make_float2(s0, s1));
                __stcs((float2*)(Ag + (size_t)(row0 + 8) * S + col), make_float2(s2, s3));
            }
        }
    }

#pragma unroll
    for (int n = 0; n < 4; n++)
#pragma unroll
        for (int h = 0; h < 2; h++) {
            float x = colacc[n][h];
            x += __shfl_xor_sync(0xffffffffu, x, 4);
            x += __shfl_xor_sync(0xffffffffu, x, 8);
            x += __shfl_xor_sync(0xffffffffu, x, 16);
            colacc[n][h] = x;
        }
    if (lane < 4) {
#pragma unroll
        for (int n = 0; n < 4; n++) {
            scr[wid * 32 + n * 8 + lane * 2]     = colacc[n][0];
            scr[wid * 32 + n * 8 + lane * 2 + 1] = colacc[n][1];
        }
    }
    __syncthreads();
    if (tid < 128) {
        int wkk = tid >> 5, c = tid & 31;
        g_NC[bh * S + kbG + wkk * 32 + c] = scr[wkk * 32 + c] + scr[(4 + wkk) * 32 + c];
    }
}

// ============================================================================
// Kernel 2: rc = rsqrt(N_C)
// ============================================================================
__global__ void k_prep() {
    int i = blockIdx.x * 256 + threadIdx.x;
    if (i < BH * S) g_RC[i] = rsqrtf(g_NC[i]);
}

// ============================================================================
// Kernel 3: rowsum + finalize, SINGLE global read via smem row cache.
// Block = 8 q-rows; each warp owns one row end-to-end:
//   cp.async row (8KB) -> smem; rowsum from smem (bfly -> rinv in-lane);
//   rescale from smem -> STG final weights. Thread-local column pattern
//   (c = step*32+lane) => no barriers at all.
// smem 64KB -> 2 CTAs/SM.
// ============================================================================
#define RS_SMEM (8 * 2048 * 4)

__global__ __launch_bounds__(256)
void k_rowscale(float* __restrict__ attn) {
    extern __shared__ float sms[];
    const int bh = blockIdx.y;
    const int q  = blockIdx.x * 8 + (threadIdx.x >> 5);
    const int l  = threadIdx.x & 31;
    const int w  = threadIdx.x >> 5;

    const float4* rc4 = (const float4*)(g_RC + bh * S);
    float* rowg = attn + (size_t)bh * S * S + (size_t)q * S;
    const u32 srow = smem_u32(sms) + (u32)w * 8192;
    const float4* srow4 = (const float4*)(sms + w * 2048);

    // stage this warp's row (each thread loads the float4s it later reads)
#pragma unroll
    for (int i = 0; i < 16; i++)
        cpa16(srow + (u32)(i * 32 + l) * 16, rowg + (i * 32 + l) * 4);
    CPA_COMMIT();
    CPA_WAIT0();

    // rowsum of s*rc
    float acc = 0.f;
#pragma unroll 4
    for (int step = 0; step < 16; step++) {
        int c = step * 32 + l;
        float4 rcv = __ldg(&rc4[c]);
        float4 sv = srow4[c];
        acc += sv.x * rcv.x + sv.y * rcv.y + sv.z * rcv.z + sv.w * rcv.w;
    }
#pragma unroll
    for (int off = 16; off; off >>= 1)
        acc += __shfl_xor_sync(0xffffffffu, acc, off);
    const float ri = 1.0f / acc;

    // finalize: w = s*rc*rinv
#pragma unroll 4
    for (int step = 0; step < 16; step++) {
        int c = step * 32 + l;
        float4 rcv = __ldg(&rc4[c]);
        float4 sv = srow4[c];
        float4 wv;
        wv.x = sv.x * rcv.x * ri;
        wv.y = sv.y * rcv.y * ri;
        wv.z = sv.z * rcv.z * ri;
        wv.w = sv.w * rcv.w * ri;
        __stcs((float4*)rowg + c, wv);
    }
}

// ============================================================================
// Kernel 4: AV via HMMA bf16x3, double-buffered. Reads FINAL weights. (unchanged)
// ============================================================================
#define PWW 40
#define WTB 10240
#define VTB 4608
#define WV_SMEM 59392
#define NI (S / 32)

__global__ __launch_bounds__(256, 2)
void k_wav_mma(const float* __restrict__ attn, float* __restrict__ Og_) {
    extern __shared__ char smc[];
    const u32 sbase = smem_u32(smc);

    const int qb = blockIdx.x * 128, bh = blockIdx.y;
    const int tid = threadIdx.x, wid = tid >> 5, lane = tid & 31;
    const int wq = wid >> 1, wd = wid & 1;
    const int grp = lane >> 2, tig = lane & 3;
    const int r8 = lane & 7, ts = lane >> 3;
    const int c4 = tid & 7, m0 = tid >> 3;

    const float* Ag = attn + (size_t)bh * S * S;
    float* Og = Og_ + (size_t)bh * S * D;
    const __nv_bfloat16* VhiG = g_Vhi + (size_t)bh * S * D;
    const __nv_bfloat16* VloG = g_Vlo + (size_t)bh * S * D;

    const u32 aOff = (u32)(((wq * 32 + (ts & 1) * 8 + r8) * PWW + (ts >> 1) * 8) * 2);
    const u32 bOff = (u32)((((ts & 1) * 8 + r8) * PADW + wd * 32 + ((ts >> 1) & 1) * 8) * 2);

    float4 pf[2][4];

    auto ldgW = [&](int it, int p) {
        int cb = it * 32;
#pragma unroll
        for (int j = 0; j < 4; j++) {
            int m = m0 + 32 * j;
            pf[p][j] = __ldcs((const float4*)(Ag + (size_t)(qb + m) * S + cb + c4 * 4));
        }
    };
    auto cpaV = [&](int it, int b) {
        int cb = it * 32;
        u32 dh = sbase + 4 * WTB + (u32)b * 2 * VTB;
        u32 dl = dh + VTB;
        int row = tid >> 3, c8 = tid & 7;
        u32 off = (u32)(row * (PADW * 2) + c8 * 16);
        cpa16(dh + off, VhiG + (size_t)(cb + row) * D + c8 * 8);
        cpa16(dl + off, VloG + (size_t)(cb + row) * D + c8 * 8);
    };

    float acc[2][4][4];
#pragma unroll
    for (int t = 0; t < 2; t++)
#pragma unroll
        for (int n = 0; n < 4; n++)
#pragma unroll
            for (int c = 0; c < 4; c++) acc[t][n][c] = 0.f;

    ldgW(0, 0);
    cpaV(0, 0);
    CPA_COMMIT();

#pragma unroll 2
    for (int it = 0; it < NI; it++) {
        const int p = it & 1, pn = p ^ 1;

        {
            __nv_bfloat16* Whi = (__nv_bfloat16*)(smc + p * 2 * WTB);
            __nv_bfloat16* Wlo = (__nv_bfloat16*)(smc + p * 2 * WTB + WTB);
#pragma unroll
            for (int j = 0; j < 4; j++) {
                int m = m0 + 32 * j;
                float4 wv = pf[p][j];
                __nv_bfloat162 h01 = __floats2bfloat162_rn(wv.x, wv.y);
                __nv_bfloat162 h23 = __floats2bfloat162_rn(wv.z, wv.w);
                __nv_bfloat162 l01 = __floats2bfloat162_rn(wv.x - __bfloat162float(h01.x),
                                                           wv.y - __bfloat162float(h01.y));
                __nv_bfloat162 l23 = __floats2bfloat162_rn(wv.z - __bfloat162float(h23.x),
                                                           wv.w - __bfloat162float(h23.y));
                *(uint2*)(Whi + m * PWW + c4 * 4) = make_uint2(*(u32*)&h01, *(u32*)&h23);
                *(uint2*)(Wlo + m * PWW + c4 * 4) = make_uint2(*(u32*)&l01, *(u32*)&l23);
            }
        }
        if (it + 1 < NI) ldgW(it + 1, pn);

        CPA_WAIT0();
        __syncthreads();
        if (it + 1 < NI) { cpaV(it + 1, pn); CPA_COMMIT(); }

        const u32 sWh = sbase + (u32)p * 2 * WTB;
        const u32 sWl = sWh + WTB;
        const u32 sVh = sbase + 4 * WTB + (u32)p * 2 * VTB;
        const u32 sVl = sVh + VTB;

#pragma unroll
        for (int ks = 0; ks < 2; ks++) {
            u32 bfh0[4], bfh1[4], bfl0[4], bfl1[4];
            ldm4t(sVh + bOff + ks * 2304, bfh0);
            ldm4t(sVh + bOff + 32 + ks * 2304, bfh1);
            ldm4t(sVl + bOff + ks * 2304, bfl0);
            ldm4t(sVl + bOff + 32 + ks * 2304, bfl1);
#pragma unroll
            for (int t = 0; t < 2; t++) {
                u32 ah[4], al[4];
                ldm4(sWh + aOff + t * 1280 + ks * 32, ah);
                ldm4(sWl + aOff + t * 1280 + ks * 32, al);
#pragma unroll
                for (int n = 0; n < 4; n++) {
                    const u32* bp = (n < 2) ? bfh0 : bfh1;
                    const u32* lp = (n < 2) ? bfl0 : bfl1;
                    int h = (n & 1) * 2;
                    mma_bf16(acc[t][n], ah, bp[h], bp[h + 1]);
                    mma_bf16(acc[t][n], ah, lp[h], lp[h + 1]);
                    mma_bf16(acc[t][n], al, bp[h], bp[h + 1]);
                }
            }
        }
    }

#pragma unroll
    for (int t = 0; t < 2; t++) {
        int row0 = qb + wq * 32 + t * 16 + grp;
#pragma unroll
        for (int n = 0; n < 4; n++) {
            int col = wd * 32 + n * 8 + tig * 2;
            *(float2*)(Og + (size_t)row0 * D + col)       = make_float2(acc[t][n][0], acc[t][n][1]);
            *(float2*)(Og + (size_t)(row0 + 8) * D + col) = make_float2(acc[t][n][2], acc[t][n][3]);
        }
    }
}

// ============================================================================
extern "C" void kernel_launch(void* const* d_in, const int* in_sizes, int n_in,
                              void* d_out, int out_size) {
    const float* q = (const float*)d_in[0];
    const float* k = (const float*)d_in[1];
    const float* v = (const float*)d_in[2];
    // d_in[3] = attn_mask (all False) — no-op in reference.

    float* out  = (float*)d_out;
    float* O    = out;                       // [B,H,S,D]
    float* attn = out + (size_t)BH * S * D;  // [B,H,S,S]

    cudaFuncSetAttribute(k_scores_mma, cudaFuncAttributeMaxDynamicSharedMemorySize, SC_SMEM);
    cudaFuncSetAttribute(k_rowscale,   cudaFuncAttributeMaxDynamicSharedMemorySize, RS_SMEM);
    cudaFuncSetAttribute(k_wav_mma,    cudaFuncAttributeMaxDynamicSharedMemorySize, WV_SMEM);

    dim3 gc((BH * S * D / 4 + 255) / 256, 3);
    k_convert<<<gc, 256>>>(q, k, v);

    dim3 g1(S / 128, BH);
    k_scores_mma<<<g1, 256, SC_SMEM>>>(attn);

    k_prep<<<(BH * S + 255) / 256, 256>>>();

    dim3 g3(S / 8, BH);
    k_rowscale<<<g3, 256, RS_SMEM>>>(attn);

    dim3 g4(S / 128, BH);
    k_wav_mma<<<g4, 256, WV_SMEM>>>(attn, O);
}